// round 4
// baseline (speedup 1.0000x reference)
#include <cuda_runtime.h>

// Fused transformer block, fp32, f32x2-packed FMAs, 512 threads.
// FFN phases row-split: each thread = 8 rows x 2 cols (halves LDS traffic).
// B=8192, T=8, C=512, H=8, HS=64, FF=2048. 2 batches per CTA (16 rows).

#define Cd 512
#define Td 8
#define Hd 8
#define HSd 64
#define FFd 2048
#define ROWS 16
#define XS 20            // padded transposed-activation stride (floats)
#define NT 512

// smem layout (floats)
#define OFF_X    0          // 16x512           = 8192
#define OFF_XN   8192       // 512 x XS         = 10240 (transposed LN out)
#define OFF_P    18432      // 16x512
#define OFF_K    26624      // 16x512
#define OFF_V    34816      // 16x512
#define OFF_WEI  43008      // 16x64
#define OFF_SAT  26624      // reuse K+V region: 512 x XS = 10240
#define SMEM_FLOATS 44032
#define SMEM_BYTES  (SMEM_FLOATS * 4)

typedef unsigned long long ull;

__device__ __forceinline__ ull pack2(float a, float b) {
    ull r; asm("mov.b64 %0, {%1, %2};" : "=l"(r) : "f"(a), "f"(b)); return r;
}
__device__ __forceinline__ void ffma2(ull &d, ull a, ull b) {
    asm("fma.rn.f32x2 %0, %1, %2, %0;" : "+l"(d) : "l"(a), "l"(b));
}
__device__ __forceinline__ float2 unpack2(ull v) {
    float2 r; asm("mov.b64 {%0, %1}, %2;" : "=f"(r.x), "=f"(r.y) : "l"(v)); return r;
}
__device__ __forceinline__ float wsum(float v) {
    #pragma unroll
    for (int m = 16; m > 0; m >>= 1) v += __shfl_xor_sync(0xffffffffu, v, m);
    return v;
}

__global__ void __launch_bounds__(NT, 1)
block_kernel(const float* __restrict__ gidx,
             const float* __restrict__ lg1, const float* __restrict__ lb1,
             const float* __restrict__ lg2, const float* __restrict__ lb2,
             const float* __restrict__ Wp, const float* __restrict__ bp,
             const float* __restrict__ Wk, const float* __restrict__ bk,
             const float* __restrict__ Wv, const float* __restrict__ bv,
             const float* __restrict__ W1, const float* __restrict__ b1f,
             const float* __restrict__ W2, const float* __restrict__ b2f,
             float* __restrict__ gout)
{
    extern __shared__ float smem[];
    float* sx   = smem + OFF_X;
    float* sxn  = smem + OFF_XN;
    float* sp   = smem + OFF_P;
    float* sk   = smem + OFF_K;
    float* sv   = smem + OFF_V;
    float* swei = smem + OFF_WEI;
    float* sat  = smem + OFF_SAT;

    const int tid  = threadIdx.x;
    const int lane = tid & 31;
    const int w    = tid >> 5;          // 0..15
    const int half = tid >> 8;          // 0 or 1 (row half for FFN)
    const int cl   = tid & 255;         // column within half-group
    const long long base = (long long)blockIdx.x * (ROWS * Cd);

    // ---- load idx tile (16 x 512) ----
    {
        const float4* gx = (const float4*)(gidx + base);
        float4* sx4 = (float4*)sx;
        #pragma unroll
        for (int i = 0; i < 4; i++) sx4[tid + i * NT] = gx[tid + i * NT];
    }
    __syncthreads();

    // ---- LN1: warp w handles row w; write transposed sxn[c][r] ----
    {
        int r = w;
        const float* xr = sx + r * Cd;
        float s1 = 0.f, s2 = 0.f;
        #pragma unroll
        for (int c = lane; c < Cd; c += 32) { float v = xr[c]; s1 += v; s2 += v * v; }
        s1 = wsum(s1); s2 = wsum(s2);
        float mean = s1 * (1.0f / Cd);
        float var  = s2 * (1.0f / Cd) - mean * mean;
        float rstd = rsqrtf(var + 1e-5f);
        #pragma unroll
        for (int c = lane; c < Cd; c += 32)
            sxn[c * XS + r] = (xr[c] - mean) * rstd * lg1[c] + lb1[c];
    }
    __syncthreads();

    // ---- QKV projections: merged k-loop, 1 col/thread, 24 FFMA2 per c ----
    {
        const int j = tid;
        const int hoff = (j >> 6) * (Cd * HSd) + (j & 63);
        const float* wpp = Wp + hoff;
        const float* wkp = Wk + hoff;
        const float* wvp = Wv + hoff;
        ull ap[8], ak[8], av[8];
        #pragma unroll
        for (int i = 0; i < 8; i++) { ap[i] = 0ull; ak[i] = 0ull; av[i] = 0ull; }
        #pragma unroll 4
        for (int c = 0; c < Cd; c++) {
            float fp = wpp[c * HSd];
            float fk = wkp[c * HSd];
            float fv = wvp[c * HSd];
            ull pp = pack2(fp, fp), pk = pack2(fk, fk), pv = pack2(fv, fv);
            const ulonglong2* xq = (const ulonglong2*)(sxn + c * XS);
            ulonglong2 q0 = xq[0], q1 = xq[1], q2 = xq[2], q3 = xq[3];
            ull xr[8] = {q0.x, q0.y, q1.x, q1.y, q2.x, q2.y, q3.x, q3.y};
            #pragma unroll
            for (int i = 0; i < 8; i++) {
                ffma2(ap[i], xr[i], pp);
                ffma2(ak[i], xr[i], pk);
                ffma2(av[i], xr[i], pv);
            }
        }
        float bjp = bp[j], bjk = bk[j], bjv = bv[j];
        #pragma unroll
        for (int i = 0; i < 8; i++) {
            float2 vp = unpack2(ap[i]), vk = unpack2(ak[i]), vv = unpack2(av[i]);
            sp[(2 * i)     * Cd + j] = vp.x + bjp;
            sp[(2 * i + 1) * Cd + j] = vp.y + bjp;
            sk[(2 * i)     * Cd + j] = vk.x + bjk;
            sk[(2 * i + 1) * Cd + j] = vk.y + bjk;
            sv[(2 * i)     * Cd + j] = vv.x + bjv;
            sv[(2 * i + 1) * Cd + j] = vv.y + bjv;
        }
    }
    __syncthreads();

    // ---- attention: warp w handles task w = (g,h) ----
    {
        int tk = w;
        int g = tk >> 3, h = tk & 7;
        #pragma unroll
        for (int hf = 0; hf < 2; hf++) {
            int idx = lane + hf * 32;
            int t = idx >> 3, s = idx & 7;
            const float4* pr = (const float4*)(sp + (g * 8 + t) * Cd + h * HSd);
            const float4* kr = (const float4*)(sk + (g * 8 + s) * Cd + h * HSd);
            float acc = 0.f;
            #pragma unroll
            for (int i = 0; i < 16; i++) {
                float4 a = pr[i], b = kr[i];
                acc += a.x * b.x + a.y * b.y + a.z * b.z + a.w * b.w;
            }
            float logit = acc * 0.125f;               // 1/sqrt(64)
            bool valid  = (s <= t);
            float ml = valid ? logit : -3.0e38f;
            float mx = ml;
            mx = fmaxf(mx, __shfl_xor_sync(0xffffffffu, mx, 1));
            mx = fmaxf(mx, __shfl_xor_sync(0xffffffffu, mx, 2));
            mx = fmaxf(mx, __shfl_xor_sync(0xffffffffu, mx, 4));
            float e = valid ? __expf(logit - mx) : 0.f;
            float sm = e;
            sm += __shfl_xor_sync(0xffffffffu, sm, 1);
            sm += __shfl_xor_sync(0xffffffffu, sm, 2);
            sm += __shfl_xor_sync(0xffffffffu, sm, 4);
            swei[tk * 64 + idx] = e / sm;
        }
    }
    __syncthreads();
    // phase B: att = wei @ v, overwrite sp
    {
        int tk = w;
        int g = tk >> 3, h = tk & 7;
        int d0 = lane, d1 = lane + 32;
        #pragma unroll
        for (int t = 0; t < 8; t++) {
            float a0 = 0.f, a1 = 0.f;
            #pragma unroll
            for (int s = 0; s < 8; s++) {
                float wv = swei[tk * 64 + t * 8 + s];
                const float* vr = sv + (g * 8 + s) * Cd + h * HSd;
                a0 += wv * vr[d0];
                a1 += wv * vr[d1];
            }
            sp[(g * 8 + t) * Cd + h * HSd + d0] = a0;
            sp[(g * 8 + t) * Cd + h * HSd + d1] = a1;
        }
    }
    __syncthreads();

    // ---- LN2 over (att + x), write transposed into sxn ----
    {
        int r = w;
        const float* ar = sp + r * Cd;
        const float* xr = sx + r * Cd;
        float s1 = 0.f, s2 = 0.f;
        #pragma unroll
        for (int c = lane; c < Cd; c += 32) { float v = ar[c] + xr[c]; s1 += v; s2 += v * v; }
        s1 = wsum(s1); s2 = wsum(s2);
        float mean = s1 * (1.0f / Cd);
        float var  = s2 * (1.0f / Cd) - mean * mean;
        float rstd = rsqrtf(var + 1e-5f);
        #pragma unroll
        for (int c = lane; c < Cd; c += 32)
            sxn[c * XS + r] = (ar[c] + xr[c] - mean) * rstd * lg2[c] + lb2[c];
    }
    __syncthreads();

    // ---- FFN: 4 chunks of 512 FF-cols; row-split: 8 rows x 2 cols per thread ----
    // thread = (half, cl): rows [8*half, 8*half+8), cols cl and cl+256 (within chunk)
    ull ob0[4], ob1[4];
    #pragma unroll
    for (int i = 0; i < 4; i++) { ob0[i] = 0ull; ob1[i] = 0ull; }

    for (int ch = 0; ch < 4; ch++) {
        const int fb = ch * 512;
        // a-phase: a[r][f] = relu(h @ W1 + b1), cols f0 = fb+cl, f1 = fb+cl+256
        {
            const int f0 = fb + cl, f1 = fb + cl + 256;
            ull a0[4], a1[4];
            #pragma unroll
            for (int i = 0; i < 4; i++) { a0[i] = 0ull; a1[i] = 0ull; }
            #pragma unroll 4
            for (int c = 0; c < Cd; c++) {
                float wa = W1[c * FFd + f0];
                float wb = W1[c * FFd + f1];
                ull pa = pack2(wa, wa), pb = pack2(wb, wb);
                const ulonglong2* xq = (const ulonglong2*)(sxn + c * XS);
                ulonglong2 q0 = xq[2 * half], q1 = xq[2 * half + 1];
                ull xr[4] = {q0.x, q0.y, q1.x, q1.y};
                #pragma unroll
                for (int i = 0; i < 4; i++) { ffma2(a0[i], xr[i], pa); ffma2(a1[i], xr[i], pb); }
            }
            float ba = b1f[f0], bb = b1f[f1];
            const int r0 = 8 * half;   // first row of this half
            #pragma unroll
            for (int i = 0; i < 4; i++) {
                float2 v0 = unpack2(a0[i]), v1 = unpack2(a1[i]);
                sat[cl         * XS + r0 + 2 * i]     = fmaxf(v0.x + ba, 0.f);
                sat[cl         * XS + r0 + 2 * i + 1] = fmaxf(v0.y + ba, 0.f);
                sat[(cl + 256) * XS + r0 + 2 * i]     = fmaxf(v1.x + bb, 0.f);
                sat[(cl + 256) * XS + r0 + 2 * i + 1] = fmaxf(v1.y + bb, 0.f);
            }
        }
        __syncthreads();
        // b-phase: out += a @ W2, cols c0 = cl, c1 = cl+256, rows of this half
        {
            #pragma unroll 4
            for (int fl = 0; fl < 512; fl++) {
                const int f = fb + fl;
                float wa = W2[f * Cd + cl];
                float wb = W2[f * Cd + cl + 256];
                ull pa = pack2(wa, wa), pb = pack2(wb, wb);
                const ulonglong2* aq = (const ulonglong2*)(sat + fl * XS);
                ulonglong2 q0 = aq[2 * half], q1 = aq[2 * half + 1];
                ull xr[4] = {q0.x, q0.y, q1.x, q1.y};
                #pragma unroll
                for (int i = 0; i < 4; i++) { ffma2(ob0[i], xr[i], pa); ffma2(ob1[i], xr[i], pb); }
            }
        }
        __syncthreads();
    }

    // ---- epilogue: out = ffn + b2 + idx (original residual) ----
    {
        const int c0 = cl, c1 = cl + 256;
        float bc0 = b2f[c0], bc1 = b2f[c1];
        float* go = gout + base;
        const int rbase = 8 * half;
        #pragma unroll
        for (int i = 0; i < 4; i++) {
            float2 v0 = unpack2(ob0[i]), v1 = unpack2(ob1[i]);
            int r0 = rbase + 2 * i, r1 = rbase + 2 * i + 1;
            go[r0 * Cd + c0] = v0.x + bc0 + sx[r0 * Cd + c0];
            go[r1 * Cd + c0] = v0.y + bc0 + sx[r1 * Cd + c0];
            go[r0 * Cd + c1] = v1.x + bc1 + sx[r0 * Cd + c1];
            go[r1 * Cd + c1] = v1.y + bc1 + sx[r1 * Cd + c1];
        }
    }
}

extern "C" void kernel_launch(void* const* d_in, const int* in_sizes, int n_in,
                              void* d_out, int out_size)
{
    (void)in_sizes; (void)n_in; (void)out_size;
    cudaFuncSetAttribute(block_kernel, cudaFuncAttributeMaxDynamicSharedMemorySize, SMEM_BYTES);
    block_kernel<<<4096, NT, SMEM_BYTES>>>(
        (const float*)d_in[0],
        (const float*)d_in[1], (const float*)d_in[2],
        (const float*)d_in[3], (const float*)d_in[4],
        (const float*)d_in[5], (const float*)d_in[6],
        (const float*)d_in[7], (const float*)d_in[8],
        (const float*)d_in[9], (const float*)d_in[10],
        (const float*)d_in[11], (const float*)d_in[12],
        (const float*)d_in[13], (const float*)d_in[14],
        (float*)d_out);
}

// round 5
// speedup vs baseline: 1.9037x; 1.9037x over previous
#include <cuda_runtime.h>

// Fused transformer block, fp32, f32x2-packed FMAs, 512 threads.
// R5: R3 structure + FFN a-phase 2-col (1024-col chunks) + pointer walking + unroll 8.
// B=8192, T=8, C=512, H=8, HS=64, FF=2048. 2 batches per CTA (16 rows).

#define Cd 512
#define Td 8
#define Hd 8
#define HSd 64
#define FFd 2048
#define ROWS 16
#define XS 20            // padded transposed-activation stride (floats)
#define NT 512

// smem layout (floats)
#define OFF_X    0          // 16x512           = 8192
#define OFF_XN   8192       // 512 x XS         = 10240 (transposed LN out)
#define OFF_P    18432      // 16x512
#define OFF_K    26624      // 16x512
#define OFF_V    34816      // 16x512
#define OFF_WEI  43008      // 16x64
#define OFF_SAT  18432      // reuse P+K+V region: 1024 x XS = 20480 floats (80KB)
#define SMEM_FLOATS 44032
#define SMEM_BYTES  (SMEM_FLOATS * 4)

typedef unsigned long long ull;

__device__ __forceinline__ ull pack2(float a, float b) {
    ull r; asm("mov.b64 %0, {%1, %2};" : "=l"(r) : "f"(a), "f"(b)); return r;
}
__device__ __forceinline__ void ffma2(ull &d, ull a, ull b) {
    asm("fma.rn.f32x2 %0, %1, %2, %0;" : "+l"(d) : "l"(a), "l"(b));
}
__device__ __forceinline__ float2 unpack2(ull v) {
    float2 r; asm("mov.b64 {%0, %1}, %2;" : "=f"(r.x), "=f"(r.y) : "l"(v)); return r;
}
__device__ __forceinline__ float wsum(float v) {
    #pragma unroll
    for (int m = 16; m > 0; m >>= 1) v += __shfl_xor_sync(0xffffffffu, v, m);
    return v;
}

__global__ void __launch_bounds__(NT, 1)
block_kernel(const float* __restrict__ gidx,
             const float* __restrict__ lg1, const float* __restrict__ lb1,
             const float* __restrict__ lg2, const float* __restrict__ lb2,
             const float* __restrict__ Wp, const float* __restrict__ bp,
             const float* __restrict__ Wk, const float* __restrict__ bk,
             const float* __restrict__ Wv, const float* __restrict__ bv,
             const float* __restrict__ W1, const float* __restrict__ b1f,
             const float* __restrict__ W2, const float* __restrict__ b2f,
             float* __restrict__ gout)
{
    extern __shared__ float smem[];
    float* sx   = smem + OFF_X;
    float* sxn  = smem + OFF_XN;
    float* sp   = smem + OFF_P;
    float* sk   = smem + OFF_K;
    float* sv   = smem + OFF_V;
    float* swei = smem + OFF_WEI;
    float* sat  = smem + OFF_SAT;

    const int tid  = threadIdx.x;
    const int lane = tid & 31;
    const int w    = tid >> 5;          // 0..15
    const long long base = (long long)blockIdx.x * (ROWS * Cd);

    // ---- load idx tile (16 x 512) ----
    {
        const float4* gx = (const float4*)(gidx + base);
        float4* sx4 = (float4*)sx;
        #pragma unroll
        for (int i = 0; i < 4; i++) sx4[tid + i * NT] = gx[tid + i * NT];
    }
    __syncthreads();

    // ---- LN1: warp w handles row w; write transposed sxn[c][r] ----
    {
        int r = w;
        const float* xr = sx + r * Cd;
        float s1 = 0.f, s2 = 0.f;
        #pragma unroll
        for (int c = lane; c < Cd; c += 32) { float v = xr[c]; s1 += v; s2 += v * v; }
        s1 = wsum(s1); s2 = wsum(s2);
        float mean = s1 * (1.0f / Cd);
        float var  = s2 * (1.0f / Cd) - mean * mean;
        float rstd = rsqrtf(var + 1e-5f);
        #pragma unroll
        for (int c = lane; c < Cd; c += 32)
            sxn[c * XS + r] = (xr[c] - mean) * rstd * lg1[c] + lb1[c];
    }
    __syncthreads();

    // ---- QKV projections: merged k-loop, 1 col/thread, 24 FFMA2 per c ----
    {
        const int j = tid;
        const int hoff = (j >> 6) * (Cd * HSd) + (j & 63);
        const float* wpp = Wp + hoff;
        const float* wkp = Wk + hoff;
        const float* wvp = Wv + hoff;
        const float* xp  = sxn;
        ull ap[8], ak[8], av[8];
        #pragma unroll
        for (int i = 0; i < 8; i++) { ap[i] = 0ull; ak[i] = 0ull; av[i] = 0ull; }
        #pragma unroll 8
        for (int c = 0; c < Cd; c++) {
            float fp = *wpp; wpp += HSd;
            float fk = *wkp; wkp += HSd;
            float fv = *wvp; wvp += HSd;
            ull pp = pack2(fp, fp), pk = pack2(fk, fk), pv = pack2(fv, fv);
            const ulonglong2* xq = (const ulonglong2*)xp; xp += XS;
            ulonglong2 q0 = xq[0], q1 = xq[1], q2 = xq[2], q3 = xq[3];
            ull xr[8] = {q0.x, q0.y, q1.x, q1.y, q2.x, q2.y, q3.x, q3.y};
            #pragma unroll
            for (int i = 0; i < 8; i++) {
                ffma2(ap[i], xr[i], pp);
                ffma2(ak[i], xr[i], pk);
                ffma2(av[i], xr[i], pv);
            }
        }
        float bjp = bp[j], bjk = bk[j], bjv = bv[j];
        #pragma unroll
        for (int i = 0; i < 8; i++) {
            float2 vp = unpack2(ap[i]), vk = unpack2(ak[i]), vv = unpack2(av[i]);
            sp[(2 * i)     * Cd + j] = vp.x + bjp;
            sp[(2 * i + 1) * Cd + j] = vp.y + bjp;
            sk[(2 * i)     * Cd + j] = vk.x + bjk;
            sk[(2 * i + 1) * Cd + j] = vk.y + bjk;
            sv[(2 * i)     * Cd + j] = vv.x + bjv;
            sv[(2 * i + 1) * Cd + j] = vv.y + bjv;
        }
    }
    __syncthreads();

    // ---- attention: warp w handles task w = (g,h) ----
    {
        int tk = w;
        int g = tk >> 3, h = tk & 7;
        #pragma unroll
        for (int hf = 0; hf < 2; hf++) {
            int idx = lane + hf * 32;
            int t = idx >> 3, s = idx & 7;
            const float4* pr = (const float4*)(sp + (g * 8 + t) * Cd + h * HSd);
            const float4* kr = (const float4*)(sk + (g * 8 + s) * Cd + h * HSd);
            float acc = 0.f;
            #pragma unroll
            for (int i = 0; i < 16; i++) {
                float4 a = pr[i], b = kr[i];
                acc += a.x * b.x + a.y * b.y + a.z * b.z + a.w * b.w;
            }
            float logit = acc * 0.125f;               // 1/sqrt(64)
            bool valid  = (s <= t);
            float ml = valid ? logit : -3.0e38f;
            float mx = ml;
            mx = fmaxf(mx, __shfl_xor_sync(0xffffffffu, mx, 1));
            mx = fmaxf(mx, __shfl_xor_sync(0xffffffffu, mx, 2));
            mx = fmaxf(mx, __shfl_xor_sync(0xffffffffu, mx, 4));
            float e = valid ? __expf(logit - mx) : 0.f;
            float sm = e;
            sm += __shfl_xor_sync(0xffffffffu, sm, 1);
            sm += __shfl_xor_sync(0xffffffffu, sm, 2);
            sm += __shfl_xor_sync(0xffffffffu, sm, 4);
            swei[tk * 64 + idx] = e / sm;
        }
    }
    __syncthreads();
    // phase B: att = wei @ v, overwrite sp
    {
        int tk = w;
        int g = tk >> 3, h = tk & 7;
        int d0 = lane, d1 = lane + 32;
        #pragma unroll
        for (int t = 0; t < 8; t++) {
            float a0 = 0.f, a1 = 0.f;
            #pragma unroll
            for (int s = 0; s < 8; s++) {
                float wv = swei[tk * 64 + t * 8 + s];
                const float* vr = sv + (g * 8 + s) * Cd + h * HSd;
                a0 += wv * vr[d0];
                a1 += wv * vr[d1];
            }
            sp[(g * 8 + t) * Cd + h * HSd + d0] = a0;
            sp[(g * 8 + t) * Cd + h * HSd + d1] = a1;
        }
    }
    __syncthreads();

    // ---- LN2 over (att + x), write transposed into sxn ----
    {
        int r = w;
        const float* ar = sp + r * Cd;
        const float* xr = sx + r * Cd;
        float s1 = 0.f, s2 = 0.f;
        #pragma unroll
        for (int c = lane; c < Cd; c += 32) { float v = ar[c] + xr[c]; s1 += v; s2 += v * v; }
        s1 = wsum(s1); s2 = wsum(s2);
        float mean = s1 * (1.0f / Cd);
        float var  = s2 * (1.0f / Cd) - mean * mean;
        float rstd = rsqrtf(var + 1e-5f);
        #pragma unroll
        for (int c = lane; c < Cd; c += 32)
            sxn[c * XS + r] = (ar[c] + xr[c] - mean) * rstd * lg2[c] + lb2[c];
    }
    __syncthreads();

    // ---- FFN: 2 chunks of 1024 FF-cols ----
    // a-phase: each thread computes 2 cols (f, f+512) x 16 rows -> sat[1024 x XS]
    // b-phase: each thread accumulates out col tid over 1024 f per chunk
    ull ob[8];
    #pragma unroll
    for (int i = 0; i < 8; i++) ob[i] = 0ull;

    #pragma unroll 1
    for (int ch = 0; ch < 2; ch++) {
        const int fb = ch * 1024;
        // a-phase
        {
            const float* w1a = W1 + fb + tid;        // col f0, row-walk stride FFd
            const float* w1b = W1 + fb + tid + 512;  // col f1
            const float* xp  = sxn;
            ull a0[8], a1[8];
            #pragma unroll
            for (int i = 0; i < 8; i++) { a0[i] = 0ull; a1[i] = 0ull; }
            #pragma unroll 8
            for (int c = 0; c < Cd; c++) {
                float wa = *w1a; w1a += FFd;
                float wb = *w1b; w1b += FFd;
                ull pa = pack2(wa, wa), pb = pack2(wb, wb);
                const ulonglong2* xq = (const ulonglong2*)xp; xp += XS;
                ulonglong2 q0 = xq[0], q1 = xq[1], q2 = xq[2], q3 = xq[3];
                ull xr[8] = {q0.x, q0.y, q1.x, q1.y, q2.x, q2.y, q3.x, q3.y};
                #pragma unroll
                for (int i = 0; i < 8; i++) { ffma2(a0[i], xr[i], pa); ffma2(a1[i], xr[i], pb); }
            }
            float ba = b1f[fb + tid], bb = b1f[fb + tid + 512];
            float* s0 = sat + tid * XS;
            float* s1p = sat + (tid + 512) * XS;
            #pragma unroll
            for (int i = 0; i < 8; i++) {
                float2 v0 = unpack2(a0[i]), v1 = unpack2(a1[i]);
                s0[2 * i]      = fmaxf(v0.x + ba, 0.f);
                s0[2 * i + 1]  = fmaxf(v0.y + ba, 0.f);
                s1p[2 * i]     = fmaxf(v1.x + bb, 0.f);
                s1p[2 * i + 1] = fmaxf(v1.y + bb, 0.f);
            }
        }
        __syncthreads();
        // b-phase
        {
            const float* w2p = W2 + (long long)fb * Cd + tid;  // row-walk stride Cd
            const float* ap  = sat;
            #pragma unroll 8
            for (int fl = 0; fl < 1024; fl++) {
                float wa = *w2p; w2p += Cd;
                ull pa = pack2(wa, wa);
                const ulonglong2* aq = (const ulonglong2*)ap; ap += XS;
                ulonglong2 q0 = aq[0], q1 = aq[1], q2 = aq[2], q3 = aq[3];
                ull xr[8] = {q0.x, q0.y, q1.x, q1.y, q2.x, q2.y, q3.x, q3.y};
                #pragma unroll
                for (int i = 0; i < 8; i++) ffma2(ob[i], xr[i], pa);
            }
        }
        __syncthreads();
    }

    // ---- epilogue: out = ffn + b2 + idx (original residual) ----
    {
        float bc = b2f[tid];
        float* go = gout + base;
        #pragma unroll
        for (int i = 0; i < 8; i++) {
            float2 v0 = unpack2(ob[i]);
            int r0 = 2 * i, r1 = 2 * i + 1;
            go[r0 * Cd + tid] = v0.x + bc + sx[r0 * Cd + tid];
            go[r1 * Cd + tid] = v0.y + bc + sx[r1 * Cd + tid];
        }
    }
}

extern "C" void kernel_launch(void* const* d_in, const int* in_sizes, int n_in,
                              void* d_out, int out_size)
{
    (void)in_sizes; (void)n_in; (void)out_size;
    cudaFuncSetAttribute(block_kernel, cudaFuncAttributeMaxDynamicSharedMemorySize, SMEM_BYTES);
    block_kernel<<<4096, NT, SMEM_BYTES>>>(
        (const float*)d_in[0],
        (const float*)d_in[1], (const float*)d_in[2],
        (const float*)d_in[3], (const float*)d_in[4],
        (const float*)d_in[5], (const float*)d_in[6],
        (const float*)d_in[7], (const float*)d_in[8],
        (const float*)d_in[9], (const float*)d_in[10],
        (const float*)d_in[11], (const float*)d_in[12],
        (const float*)d_in[13], (const float*)d_in[14],
        (float*)d_out);
}

// round 8
// speedup vs baseline: 3.6016x; 1.8920x over previous
#include <cuda_runtime.h>
#include <cuda_bf16.h>
#include <cstdint>

// ============================================================================
// Hybrid: scalar fused front (LN1+QKV+attention+LN2) + HMMA split-bf16 FFN.
// mma.sync.m16n8k16 (sm_80+ PTX; no tcgen05 — harness targets plain sm_103).
// B=8192, T=8, C=512, H=8, HS=64, FF=2048.  M_total = 65536 rows.
// ============================================================================

#define Cd 512
#define Td 8
#define Hd 8
#define HSd 64
#define FFd 2048
#define ROWS 16
#define XS 20
#define NT 512
#define MTOT 65536

// ---- device scratch (static globals; no runtime allocation) ----
__device__ __nv_bfloat16 g_h_hi[(size_t)MTOT * Cd];
__device__ __nv_bfloat16 g_h_lo[(size_t)MTOT * Cd];
__device__ __nv_bfloat16 g_a_hi[(size_t)MTOT * FFd];
__device__ __nv_bfloat16 g_a_lo[(size_t)MTOT * FFd];
__device__ __nv_bfloat16 g_w1t_hi[FFd * Cd];
__device__ __nv_bfloat16 g_w1t_lo[FFd * Cd];
__device__ __nv_bfloat16 g_w2t_hi[Cd * FFd];
__device__ __nv_bfloat16 g_w2t_lo[Cd * FFd];

// ---- front kernel smem layout (floats) ----
#define OFF_X    0
#define OFF_XN   8192
#define OFF_P    18432
#define OFF_K    26624
#define OFF_V    34816
#define OFF_WEI  43008
#define F_SMEM_FLOATS 44032
#define F_SMEM_BYTES  (F_SMEM_FLOATS * 4)

typedef unsigned long long ull;

__device__ __forceinline__ ull pack2(float a, float b) {
    ull r; asm("mov.b64 %0, {%1, %2};" : "=l"(r) : "f"(a), "f"(b)); return r;
}
__device__ __forceinline__ void ffma2(ull &d, ull a, ull b) {
    asm("fma.rn.f32x2 %0, %1, %2, %0;" : "+l"(d) : "l"(a), "l"(b));
}
__device__ __forceinline__ float2 unpack2(ull v) {
    float2 r; asm("mov.b64 {%0, %1}, %2;" : "=f"(r.x), "=f"(r.y) : "l"(v)); return r;
}
__device__ __forceinline__ float wsum(float v) {
    #pragma unroll
    for (int m = 16; m > 0; m >>= 1) v += __shfl_xor_sync(0xffffffffu, v, m);
    return v;
}

// ============================================================================
// Front kernel: LN1 -> QKV -> attention -> LN2 -> write h (bf16 hi/lo)
// ============================================================================
__global__ void __launch_bounds__(NT, 1)
front_kernel(const float* __restrict__ gidx,
             const float* __restrict__ lg1, const float* __restrict__ lb1,
             const float* __restrict__ lg2, const float* __restrict__ lb2,
             const float* __restrict__ Wp, const float* __restrict__ bp,
             const float* __restrict__ Wk, const float* __restrict__ bk,
             const float* __restrict__ Wv, const float* __restrict__ bv)
{
    extern __shared__ float smem[];
    float* sx   = smem + OFF_X;
    float* sxn  = smem + OFF_XN;
    float* sp   = smem + OFF_P;
    float* sk   = smem + OFF_K;
    float* sv   = smem + OFF_V;
    float* swei = smem + OFF_WEI;

    const int tid  = threadIdx.x;
    const int lane = tid & 31;
    const int w    = tid >> 5;
    const long long base = (long long)blockIdx.x * (ROWS * Cd);

    {
        const float4* gx = (const float4*)(gidx + base);
        float4* sx4 = (float4*)sx;
        #pragma unroll
        for (int i = 0; i < 4; i++) sx4[tid + i * NT] = gx[tid + i * NT];
    }
    __syncthreads();

    // LN1
    {
        int r = w;
        const float* xr = sx + r * Cd;
        float s1 = 0.f, s2 = 0.f;
        #pragma unroll
        for (int c = lane; c < Cd; c += 32) { float v = xr[c]; s1 += v; s2 += v * v; }
        s1 = wsum(s1); s2 = wsum(s2);
        float mean = s1 * (1.0f / Cd);
        float var  = s2 * (1.0f / Cd) - mean * mean;
        float rstd = rsqrtf(var + 1e-5f);
        #pragma unroll
        for (int c = lane; c < Cd; c += 32)
            sxn[c * XS + r] = (xr[c] - mean) * rstd * lg1[c] + lb1[c];
    }
    __syncthreads();

    // QKV merged
    {
        const int j = tid;
        const int hoff = (j >> 6) * (Cd * HSd) + (j & 63);
        const float* wpp = Wp + hoff;
        const float* wkp = Wk + hoff;
        const float* wvp = Wv + hoff;
        const float* xp  = sxn;
        ull ap[8], ak[8], av[8];
        #pragma unroll
        for (int i = 0; i < 8; i++) { ap[i] = 0ull; ak[i] = 0ull; av[i] = 0ull; }
        #pragma unroll 8
        for (int c = 0; c < Cd; c++) {
            float fp = *wpp; wpp += HSd;
            float fk = *wkp; wkp += HSd;
            float fv = *wvp; wvp += HSd;
            ull pp = pack2(fp, fp), pk = pack2(fk, fk), pv = pack2(fv, fv);
            const ulonglong2* xq = (const ulonglong2*)xp; xp += XS;
            ulonglong2 q0 = xq[0], q1 = xq[1], q2 = xq[2], q3 = xq[3];
            ull xr[8] = {q0.x, q0.y, q1.x, q1.y, q2.x, q2.y, q3.x, q3.y};
            #pragma unroll
            for (int i = 0; i < 8; i++) {
                ffma2(ap[i], xr[i], pp);
                ffma2(ak[i], xr[i], pk);
                ffma2(av[i], xr[i], pv);
            }
        }
        float bjp = bp[j], bjk = bk[j], bjv = bv[j];
        #pragma unroll
        for (int i = 0; i < 8; i++) {
            float2 vp = unpack2(ap[i]), vk = unpack2(ak[i]), vv = unpack2(av[i]);
            sp[(2 * i)     * Cd + j] = vp.x + bjp;
            sp[(2 * i + 1) * Cd + j] = vp.y + bjp;
            sk[(2 * i)     * Cd + j] = vk.x + bjk;
            sk[(2 * i + 1) * Cd + j] = vk.y + bjk;
            sv[(2 * i)     * Cd + j] = vv.x + bjv;
            sv[(2 * i + 1) * Cd + j] = vv.y + bjv;
        }
    }
    __syncthreads();

    // attention phase A
    {
        int tk = w;
        int g = tk >> 3, h = tk & 7;
        #pragma unroll
        for (int hf = 0; hf < 2; hf++) {
            int idx = lane + hf * 32;
            int t = idx >> 3, s = idx & 7;
            const float4* pr = (const float4*)(sp + (g * 8 + t) * Cd + h * HSd);
            const float4* kr = (const float4*)(sk + (g * 8 + s) * Cd + h * HSd);
            float acc = 0.f;
            #pragma unroll
            for (int i = 0; i < 16; i++) {
                float4 a = pr[i], b = kr[i];
                acc += a.x * b.x + a.y * b.y + a.z * b.z + a.w * b.w;
            }
            float logit = acc * 0.125f;
            bool valid  = (s <= t);
            float ml = valid ? logit : -3.0e38f;
            float mx = ml;
            mx = fmaxf(mx, __shfl_xor_sync(0xffffffffu, mx, 1));
            mx = fmaxf(mx, __shfl_xor_sync(0xffffffffu, mx, 2));
            mx = fmaxf(mx, __shfl_xor_sync(0xffffffffu, mx, 4));
            float e = valid ? __expf(logit - mx) : 0.f;
            float sm = e;
            sm += __shfl_xor_sync(0xffffffffu, sm, 1);
            sm += __shfl_xor_sync(0xffffffffu, sm, 2);
            sm += __shfl_xor_sync(0xffffffffu, sm, 4);
            swei[tk * 64 + idx] = e / sm;
        }
    }
    __syncthreads();
    // attention phase B
    {
        int tk = w;
        int g = tk >> 3, h = tk & 7;
        int d0 = lane, d1 = lane + 32;
        #pragma unroll
        for (int t = 0; t < 8; t++) {
            float a0 = 0.f, a1 = 0.f;
            #pragma unroll
            for (int s = 0; s < 8; s++) {
                float wv = swei[tk * 64 + t * 8 + s];
                const float* vr = sv + (g * 8 + s) * Cd + h * HSd;
                a0 += wv * vr[d0];
                a1 += wv * vr[d1];
            }
            sp[(g * 8 + t) * Cd + h * HSd + d0] = a0;
            sp[(g * 8 + t) * Cd + h * HSd + d1] = a1;
        }
    }
    __syncthreads();

    // LN2 -> h hi/lo
    {
        int r = w;
        const float* ar = sp + r * Cd;
        const float* xr = sx + r * Cd;
        float s1 = 0.f, s2 = 0.f;
        #pragma unroll
        for (int c = lane; c < Cd; c += 32) { float v = ar[c] + xr[c]; s1 += v; s2 += v * v; }
        s1 = wsum(s1); s2 = wsum(s2);
        float mean = s1 * (1.0f / Cd);
        float var  = s2 * (1.0f / Cd) - mean * mean;
        float rstd = rsqrtf(var + 1e-5f);
        long long grow = (long long)blockIdx.x * ROWS + r;
        #pragma unroll
        for (int c = lane; c < Cd; c += 32) {
            float v = (ar[c] + xr[c] - mean) * rstd * lg2[c] + lb2[c];
            __nv_bfloat16 hi = __float2bfloat16(v);
            float lov = v - __bfloat162float(hi);
            g_h_hi[grow * Cd + c] = hi;
            g_h_lo[grow * Cd + c] = __float2bfloat16(lov);
        }
    }
}

// ============================================================================
// Weight conversion: transpose + bf16 hi/lo split
// ============================================================================
__global__ void convert_weights(const float* __restrict__ W1, const float* __restrict__ W2)
{
    int i = blockIdx.x * 256 + threadIdx.x;      // 0 .. 1048575
    {
        int n = i >> 9, k = i & 511;             // W1t [2048 x 512]
        float v = W1[k * FFd + n];
        __nv_bfloat16 hi = __float2bfloat16(v);
        g_w1t_hi[i] = hi;
        g_w1t_lo[i] = __float2bfloat16(v - __bfloat162float(hi));
    }
    {
        int n = i >> 11, k = i & 2047;           // W2t [512 x 2048]
        float v = W2[k * Cd + n];
        __nv_bfloat16 hi = __float2bfloat16(v);
        g_w2t_hi[i] = hi;
        g_w2t_lo[i] = __float2bfloat16(v - __bfloat162float(hi));
    }
}

// ============================================================================
// HMMA split-bf16 GEMM: CTA tile 128x128, K-chunk 32, double-buffered smem.
// A [M x K] row-major (hi/lo), B [N x K] row-major (hi/lo).
// D = AhiBhi^T + AhiBlo^T + AloBhi^T  (fp32 accum)
// epi 0: relu(d + bias[n]) -> split bf16 to g_a   (FFN1)
// epi 1: d + bias[n] + resid -> fp32 out           (FFN2)
// ============================================================================

#define KC 32
#define SROW 40                       // padded smem row stride (bf16 elems) = 80 bytes
#define MATB (128 * SROW * 2)         // 10240 bytes per matrix tile
#define GSTAGE (4 * MATB)             // Ahi|Alo|Bhi|Blo = 40960 bytes
#define G_SMEM (2 * GSTAGE)           // 81920

__device__ __forceinline__ uint32_t smem_u32(const void* p) {
    uint32_t a;
    asm("{ .reg .u64 t; cvta.to.shared.u64 t, %1; cvt.u32.u64 %0, t; }" : "=r"(a) : "l"(p));
    return a;
}
__device__ __forceinline__ void ldm_x4(uint32_t* r, uint32_t addr) {
    asm volatile("ldmatrix.sync.aligned.m8n8.x4.shared.b16 {%0,%1,%2,%3}, [%4];"
                 : "=r"(r[0]), "=r"(r[1]), "=r"(r[2]), "=r"(r[3]) : "r"(addr));
}
__device__ __forceinline__ void mma16816(float* c, const uint32_t* a, const uint32_t* b) {
    asm volatile("mma.sync.aligned.m16n8k16.row.col.f32.bf16.bf16.f32 "
                 "{%0,%1,%2,%3}, {%4,%5,%6,%7}, {%8,%9}, {%0,%1,%2,%3};"
                 : "+f"(c[0]), "+f"(c[1]), "+f"(c[2]), "+f"(c[3])
                 : "r"(a[0]), "r"(a[1]), "r"(a[2]), "r"(a[3]), "r"(b[0]), "r"(b[1]));
}

__global__ void __launch_bounds__(256, 2)
gemm_kernel(const float* __restrict__ bias, const float* __restrict__ resid,
            float* __restrict__ Of, int K, int NTOT, int epi)
{
    extern __shared__ char gsm[];
    const int tid  = threadIdx.x;
    const int lane = tid & 31;
    const int wid  = tid >> 5;
    const int wm   = wid >> 1;        // 0..3  (M subtile)
    const int wn   = wid & 1;         // 0..1  (N subtile)
    const long long mbase = (long long)blockIdx.x * 128;
    const int nbase = blockIdx.y * 128;
    const int NC = K / KC;

    const __nv_bfloat16* Ahi = epi ? g_a_hi : g_h_hi;
    const __nv_bfloat16* Alo = epi ? g_a_lo : g_h_lo;
    const __nv_bfloat16* Bhi = epi ? g_w2t_hi : g_w1t_hi;
    const __nv_bfloat16* Blo = epi ? g_w2t_lo : g_w1t_lo;

    float acc[2][8][4];
    #pragma unroll
    for (int mi = 0; mi < 2; mi++)
        #pragma unroll
        for (int j = 0; j < 8; j++)
            #pragma unroll
            for (int v = 0; v < 4; v++) acc[mi][j][v] = 0.f;

    // loader lambda: chunk kb -> stage s
    const int lrow = tid >> 2, lo16 = (tid & 3) * 16, lk8 = (tid & 3) * 8;
    #define LOAD_CHUNK(kb, s) do {                                              \
        char* _s = (s);                                                         \
        long long ga = (mbase + lrow) * (long long)K + (kb) + lk8;              \
        long long gb = (long long)(nbase + lrow) * K + (kb) + lk8;              \
        uint32_t so = lrow * (SROW * 2) + lo16;                                 \
        *(uint4*)(_s + so)            = *(const uint4*)(Ahi + ga);              \
        *(uint4*)(_s + MATB + so)     = *(const uint4*)(Alo + ga);              \
        *(uint4*)(_s + 2 * MATB + so) = *(const uint4*)(Bhi + gb);              \
        *(uint4*)(_s + 3 * MATB + so) = *(const uint4*)(Blo + gb);              \
        long long ga2 = (mbase + 64 + lrow) * (long long)K + (kb) + lk8;        \
        long long gb2 = (long long)(nbase + 64 + lrow) * K + (kb) + lk8;        \
        uint32_t so2 = (64 + lrow) * (SROW * 2) + lo16;                         \
        *(uint4*)(_s + so2)            = *(const uint4*)(Ahi + ga2);            \
        *(uint4*)(_s + MATB + so2)     = *(const uint4*)(Alo + ga2);            \
        *(uint4*)(_s + 2 * MATB + so2) = *(const uint4*)(Bhi + gb2);            \
        *(uint4*)(_s + 3 * MATB + so2) = *(const uint4*)(Blo + gb2);            \
    } while (0)

    LOAD_CHUNK(0, gsm);
    __syncthreads();

    // per-lane ldmatrix address components
    const int arow = lane & 15;
    const int asel = (lane >> 4) << 3;               // 0 or 8
    const int br   = lane & 7;
    const int bsel = (lane >> 3) & 3;
    const int bno  = br + ((bsel >> 1) << 3);        // n offset within 16
    const int bko  = (bsel & 1) << 3;                // k offset within 16

    for (int c = 0; c < NC; c++) {
        if (c + 1 < NC) LOAD_CHUNK((c + 1) * KC, gsm + ((c + 1) & 1) * GSTAGE);

        const uint32_t sb = smem_u32(gsm + (c & 1) * GSTAGE);
        #pragma unroll
        for (int ks = 0; ks < 2; ks++) {
            uint32_t ahi[2][4], alo[2][4];
            const int acol = ks * 16 + asel;
            #pragma unroll
            for (int mi = 0; mi < 2; mi++) {
                uint32_t aoff = ((wm * 32 + mi * 16 + arow) * SROW + acol) * 2;
                ldm_x4(ahi[mi], sb + aoff);
                ldm_x4(alo[mi], sb + MATB + aoff);
            }
            #pragma unroll
            for (int jj = 0; jj < 4; jj++) {
                uint32_t bhi[4], blo[4];
                uint32_t boff = ((wn * 64 + jj * 16 + bno) * SROW + ks * 16 + bko) * 2;
                ldm_x4(bhi, sb + 2 * MATB + boff);
                ldm_x4(blo, sb + 3 * MATB + boff);
                #pragma unroll
                for (int mi = 0; mi < 2; mi++) {
                    mma16816(acc[mi][2 * jj],     ahi[mi], bhi);
                    mma16816(acc[mi][2 * jj],     ahi[mi], blo);
                    mma16816(acc[mi][2 * jj],     alo[mi], bhi);
                    mma16816(acc[mi][2 * jj + 1], ahi[mi], bhi + 2);
                    mma16816(acc[mi][2 * jj + 1], ahi[mi], blo + 2);
                    mma16816(acc[mi][2 * jj + 1], alo[mi], bhi + 2);
                }
            }
        }
        __syncthreads();
    }

    // ---- epilogue ----
    const int r0 = wm * 32 + (lane >> 2);
    const int cn = wn * 64 + ((lane & 3) << 1);
    #pragma unroll
    for (int mi = 0; mi < 2; mi++) {
        #pragma unroll
        for (int j = 0; j < 8; j++) {
            int col = nbase + cn + j * 8;
            float b0 = bias[col], b1 = bias[col + 1];
            long long rg0 = mbase + r0 + mi * 16;
            long long rg1 = rg0 + 8;
            float* d = acc[mi][j];
            if (epi == 0) {
                float v00 = fmaxf(d[0] + b0, 0.f), v01 = fmaxf(d[1] + b1, 0.f);
                float v10 = fmaxf(d[2] + b0, 0.f), v11 = fmaxf(d[3] + b1, 0.f);
                __nv_bfloat16 h00 = __float2bfloat16(v00), h01 = __float2bfloat16(v01);
                __nv_bfloat16 h10 = __float2bfloat16(v10), h11 = __float2bfloat16(v11);
                *(__nv_bfloat162*)(g_a_hi + rg0 * NTOT + col) = __nv_bfloat162(h00, h01);
                *(__nv_bfloat162*)(g_a_hi + rg1 * NTOT + col) = __nv_bfloat162(h10, h11);
                *(__nv_bfloat162*)(g_a_lo + rg0 * NTOT + col) =
                    __nv_bfloat162(__float2bfloat16(v00 - __bfloat162float(h00)),
                                   __float2bfloat16(v01 - __bfloat162float(h01)));
                *(__nv_bfloat162*)(g_a_lo + rg1 * NTOT + col) =
                    __nv_bfloat162(__float2bfloat16(v10 - __bfloat162float(h10)),
                                   __float2bfloat16(v11 - __bfloat162float(h11)));
            } else {
                const float2 rv0 = *(const float2*)(resid + rg0 * NTOT + col);
                const float2 rv1 = *(const float2*)(resid + rg1 * NTOT + col);
                float2 o0 = make_float2(d[0] + b0 + rv0.x, d[1] + b1 + rv0.y);
                float2 o1 = make_float2(d[2] + b0 + rv1.x, d[3] + b1 + rv1.y);
                *(float2*)(Of + rg0 * NTOT + col) = o0;
                *(float2*)(Of + rg1 * NTOT + col) = o1;
            }
        }
    }
}

// ============================================================================
// launch
// ============================================================================
extern "C" void kernel_launch(void* const* d_in, const int* in_sizes, int n_in,
                              void* d_out, int out_size)
{
    (void)in_sizes; (void)n_in; (void)out_size;
    const float* gidx = (const float*)d_in[0];
    const float* lg1  = (const float*)d_in[1];
    const float* lb1  = (const float*)d_in[2];
    const float* lg2  = (const float*)d_in[3];
    const float* lb2  = (const float*)d_in[4];
    const float* Wp   = (const float*)d_in[5];
    const float* bp   = (const float*)d_in[6];
    const float* Wk   = (const float*)d_in[7];
    const float* bk   = (const float*)d_in[8];
    const float* Wv   = (const float*)d_in[9];
    const float* bv   = (const float*)d_in[10];
    const float* W1   = (const float*)d_in[11];
    const float* b1f  = (const float*)d_in[12];
    const float* W2   = (const float*)d_in[13];
    const float* b2f  = (const float*)d_in[14];
    float* out = (float*)d_out;

    cudaFuncSetAttribute(front_kernel, cudaFuncAttributeMaxDynamicSharedMemorySize, F_SMEM_BYTES);
    cudaFuncSetAttribute(gemm_kernel, cudaFuncAttributeMaxDynamicSharedMemorySize, G_SMEM);

    convert_weights<<<4096, 256>>>(W1, W2);
    front_kernel<<<4096, NT, F_SMEM_BYTES>>>(gidx, lg1, lb1, lg2, lb2,
                                             Wp, bp, Wk, bk, Wv, bv);
    // FFN1: [65536 x 512] @ W1t[2048 x 512]^T -> relu -> g_a (hi/lo)
    gemm_kernel<<<dim3(MTOT / 128, FFd / 128), 256, G_SMEM>>>(b1f, nullptr, nullptr, Cd, FFd, 0);
    // FFN2: [65536 x 2048] @ W2t[512 x 2048]^T + b2 + idx -> out
    gemm_kernel<<<dim3(MTOT / 128, Cd / 128), 256, G_SMEM>>>(b2f, gidx, out, FFd, Cd, 1);
}

// round 10
// speedup vs baseline: 4.3248x; 1.2008x over previous
#include <cuda_runtime.h>
#include <cuda_bf16.h>
#include <cstdint>

// ============================================================================
// All-HMMA pipeline: LN1 -> QKV GEMM -> attention+LN2 -> FFN1 GEMM -> FFN2 GEMM
// mma.sync.m16n8k16 split-bf16 (hi/lo, 3 cross terms, fp32 accum).
// B=8192, T=8, C=512, H=8, HS=64, FF=2048.  M_total = 65536 rows.
// ============================================================================

#define Cd 512
#define Td 8
#define Hd 8
#define HSd 64
#define FFd 2048
#define NQKV 1536
#define MTOT 65536

// ---- device scratch ----
__device__ __nv_bfloat16 g_xn_hi[(size_t)MTOT * Cd];
__device__ __nv_bfloat16 g_xn_lo[(size_t)MTOT * Cd];
__device__ float         g_pkv[(size_t)MTOT * NQKV];
__device__ __nv_bfloat16 g_h_hi[(size_t)MTOT * Cd];
__device__ __nv_bfloat16 g_h_lo[(size_t)MTOT * Cd];
__device__ __nv_bfloat16 g_a_hi[(size_t)MTOT * FFd];
__device__ __nv_bfloat16 g_a_lo[(size_t)MTOT * FFd];
__device__ __nv_bfloat16 g_w1t_hi[FFd * Cd];
__device__ __nv_bfloat16 g_w1t_lo[FFd * Cd];
__device__ __nv_bfloat16 g_w2t_hi[Cd * FFd];
__device__ __nv_bfloat16 g_w2t_lo[Cd * FFd];
__device__ __nv_bfloat16 g_wqkvt_hi[NQKV * Cd];
__device__ __nv_bfloat16 g_wqkvt_lo[NQKV * Cd];
__device__ float         g_bqkv[NQKV];

__device__ __forceinline__ float wsum(float v) {
    #pragma unroll
    for (int m = 16; m > 0; m >>= 1) v += __shfl_xor_sync(0xffffffffu, v, m);
    return v;
}

// ============================================================================
// Weight conversion: transpose + bf16 hi/lo split (W1, W2, Wqkv, bqkv)
// ============================================================================
__global__ void convert_weights(const float* __restrict__ W1, const float* __restrict__ W2,
                                const float* __restrict__ Wp, const float* __restrict__ Wk,
                                const float* __restrict__ Wv, const float* __restrict__ bp,
                                const float* __restrict__ bk, const float* __restrict__ bv)
{
    int i = blockIdx.x * 256 + threadIdx.x;      // 0 .. 1048575
    {
        int n = i >> 9, k = i & 511;             // W1t [2048 x 512]
        float v = W1[k * FFd + n];
        __nv_bfloat16 hi = __float2bfloat16(v);
        g_w1t_hi[i] = hi;
        g_w1t_lo[i] = __float2bfloat16(v - __bfloat162float(hi));
    }
    {
        int n = i >> 11, k = i & 2047;           // W2t [512 x 2048]
        float v = W2[k * Cd + n];
        __nv_bfloat16 hi = __float2bfloat16(v);
        g_w2t_hi[i] = hi;
        g_w2t_lo[i] = __float2bfloat16(v - __bfloat162float(hi));
    }
    if (i < NQKV * Cd) {                          // Wqkvt [1536 x 512]
        int n = i >> 9, k = i & 511;
        float v;
        if (n < 512)       v = Wp[(n >> 6) * (Cd * HSd) + k * HSd + (n & 63)];
        else if (n < 1024) { int m = n - 512;  v = Wk[(m >> 6) * (Cd * HSd) + k * HSd + (m & 63)]; }
        else               { int m = n - 1024; v = Wv[(m >> 6) * (Cd * HSd) + k * HSd + (m & 63)]; }
        __nv_bfloat16 hi = __float2bfloat16(v);
        g_wqkvt_hi[i] = hi;
        g_wqkvt_lo[i] = __float2bfloat16(v - __bfloat162float(hi));
    }
    if (i < NQKV) {
        float v;
        if (i < 512)       v = bp[i];
        else if (i < 1024) v = bk[i - 512];
        else               v = bv[i - 1024];
        g_bqkv[i] = v;
    }
}

// ============================================================================
// LN1: one warp per row; write x̂ as bf16 hi/lo
// ============================================================================
__global__ void __launch_bounds__(256)
ln1_kernel(const float* __restrict__ gidx,
           const float* __restrict__ lg1, const float* __restrict__ lb1)
{
    const long long row = (long long)blockIdx.x * 8 + (threadIdx.x >> 5);
    const int lane = threadIdx.x & 31;
    const float* xr = gidx + row * Cd;
    float s1 = 0.f, s2 = 0.f;
    #pragma unroll
    for (int c = lane; c < Cd; c += 32) { float v = xr[c]; s1 += v; s2 += v * v; }
    s1 = wsum(s1); s2 = wsum(s2);
    float mean = s1 * (1.0f / Cd);
    float var  = s2 * (1.0f / Cd) - mean * mean;
    float rstd = rsqrtf(var + 1e-5f);
    #pragma unroll
    for (int c = lane; c < Cd; c += 32) {
        float v = (xr[c] - mean) * rstd * lg1[c] + lb1[c];
        __nv_bfloat16 hi = __float2bfloat16(v);
        g_xn_hi[row * Cd + c] = hi;
        g_xn_lo[row * Cd + c] = __float2bfloat16(v - __bfloat162float(hi));
    }
}

// ============================================================================
// Attention + LN2: block = one batch (8 warps = 8 heads, then 8 tokens)
// smem: spkv[8][1536] | satt[8][512] | sxr[8][512] | swei[8][64]
// ============================================================================
#define AT_SPKV 0
#define AT_SATT (8 * 1536)
#define AT_SXR  (AT_SATT + 8 * 512)
#define AT_SW   (AT_SXR + 8 * 512)
#define AT_FLOATS (AT_SW + 8 * 64)
#define AT_SMEM (AT_FLOATS * 4)

__global__ void __launch_bounds__(256, 1)
attn_kernel(const float* __restrict__ gidx,
            const float* __restrict__ lg2, const float* __restrict__ lb2)
{
    extern __shared__ float sm[];
    float* spkv = sm + AT_SPKV;
    float* satt = sm + AT_SATT;
    float* sxr  = sm + AT_SXR;
    float* swei = sm + AT_SW;

    const int tid  = threadIdx.x;
    const int lane = tid & 31;
    const int w    = tid >> 5;          // 0..7
    const long long b = blockIdx.x;     // batch

    // load pkv slab (8 x 1536) and idx rows (8 x 512)
    {
        const float4* src = (const float4*)(g_pkv + b * 8 * NQKV);
        float4* dst = (float4*)spkv;
        #pragma unroll
        for (int i = 0; i < 12; i++) dst[tid + 256 * i] = src[tid + 256 * i];
        const float4* xs = (const float4*)(gidx + b * 8 * Cd);
        float4* xd = (float4*)sxr;
        #pragma unroll
        for (int i = 0; i < 4; i++) xd[tid + 256 * i] = xs[tid + 256 * i];
    }
    __syncthreads();

    // attention: warp w = head h
    {
        const int h = w;
        #pragma unroll
        for (int hf = 0; hf < 2; hf++) {
            int idx = lane + hf * 32;
            int t = idx >> 3, s = idx & 7;
            const float4* pr = (const float4*)(spkv + t * NQKV + h * HSd);
            const float4* kr = (const float4*)(spkv + s * NQKV + 512 + h * HSd);
            float acc = 0.f;
            #pragma unroll
            for (int i = 0; i < 16; i++) {
                float4 a = pr[i], c = kr[i];
                acc += a.x * c.x + a.y * c.y + a.z * c.z + a.w * c.w;
            }
            float logit = acc * 0.125f;
            bool valid  = (s <= t);
            float ml = valid ? logit : -3.0e38f;
            float mx = ml;
            mx = fmaxf(mx, __shfl_xor_sync(0xffffffffu, mx, 1));
            mx = fmaxf(mx, __shfl_xor_sync(0xffffffffu, mx, 2));
            mx = fmaxf(mx, __shfl_xor_sync(0xffffffffu, mx, 4));
            float e = valid ? __expf(logit - mx) : 0.f;
            float smv = e;
            smv += __shfl_xor_sync(0xffffffffu, smv, 1);
            smv += __shfl_xor_sync(0xffffffffu, smv, 2);
            smv += __shfl_xor_sync(0xffffffffu, smv, 4);
            swei[w * 64 + idx] = e / smv;
        }
        __syncwarp();
        const int d0 = lane, d1 = lane + 32;
        #pragma unroll
        for (int t = 0; t < 8; t++) {
            float a0 = 0.f, a1 = 0.f;
            #pragma unroll
            for (int s = 0; s < 8; s++) {
                float wv = swei[w * 64 + t * 8 + s];
                const float* vr = spkv + s * NQKV + 1024 + h * HSd;
                a0 += wv * vr[d0];
                a1 += wv * vr[d1];
            }
            satt[t * Cd + h * HSd + d0] = a0;
            satt[t * Cd + h * HSd + d1] = a1;
        }
    }
    __syncthreads();

    // LN2: warp w = token t; over (att + idx); write h hi/lo
    {
        const int t = w;
        const float* ar = satt + t * Cd;
        const float* xr = sxr + t * Cd;
        float s1 = 0.f, s2 = 0.f;
        #pragma unroll
        for (int c = lane; c < Cd; c += 32) { float v = ar[c] + xr[c]; s1 += v; s2 += v * v; }
        s1 = wsum(s1); s2 = wsum(s2);
        float mean = s1 * (1.0f / Cd);
        float var  = s2 * (1.0f / Cd) - mean * mean;
        float rstd = rsqrtf(var + 1e-5f);
        const long long row = b * 8 + t;
        #pragma unroll
        for (int c = lane; c < Cd; c += 32) {
            float v = (ar[c] + xr[c] - mean) * rstd * lg2[c] + lb2[c];
            __nv_bfloat16 hi = __float2bfloat16(v);
            g_h_hi[row * Cd + c] = hi;
            g_h_lo[row * Cd + c] = __float2bfloat16(v - __bfloat162float(hi));
        }
    }
}

// ============================================================================
// HMMA split-bf16 GEMM: CTA tile 128x128, K-chunk 32, double-buffered smem.
// epi 0: FFN1  A=g_h,  B=w1t,   relu(d+bias) -> split to g_a
// epi 1: FFN2  A=g_a,  B=w2t,   d+bias+resid -> Of (fp32)
// epi 2: QKV   A=g_xn, B=wqkvt, d+g_bqkv     -> g_pkv (fp32)
// ============================================================================

#define KC 32
#define SROW 40
#define MATB (128 * SROW * 2)
#define GSTAGE (4 * MATB)
#define G_SMEM (2 * GSTAGE)

__device__ __forceinline__ uint32_t smem_u32(const void* p) {
    uint32_t a;
    asm("{ .reg .u64 t; cvta.to.shared.u64 t, %1; cvt.u32.u64 %0, t; }" : "=r"(a) : "l"(p));
    return a;
}
__device__ __forceinline__ void ldm_x4(uint32_t* r, uint32_t addr) {
    asm volatile("ldmatrix.sync.aligned.m8n8.x4.shared.b16 {%0,%1,%2,%3}, [%4];"
                 : "=r"(r[0]), "=r"(r[1]), "=r"(r[2]), "=r"(r[3]) : "r"(addr));
}
__device__ __forceinline__ void mma16816(float* c, const uint32_t* a, const uint32_t* b) {
    asm volatile("mma.sync.aligned.m16n8k16.row.col.f32.bf16.bf16.f32 "
                 "{%0,%1,%2,%3}, {%4,%5,%6,%7}, {%8,%9}, {%0,%1,%2,%3};"
                 : "+f"(c[0]), "+f"(c[1]), "+f"(c[2]), "+f"(c[3])
                 : "r"(a[0]), "r"(a[1]), "r"(a[2]), "r"(a[3]), "r"(b[0]), "r"(b[1]));
}

__global__ void __launch_bounds__(256, 2)
gemm_kernel(const float* __restrict__ bias, const float* __restrict__ resid,
            float* __restrict__ Of, int K, int NTOT, int epi)
{
    extern __shared__ char gsm[];
    const int tid  = threadIdx.x;
    const int lane = tid & 31;
    const int wid  = tid >> 5;
    const int wm   = wid >> 1;
    const int wn   = wid & 1;
    const long long mbase = (long long)blockIdx.x * 128;
    const int nbase = blockIdx.y * 128;
    const int NC = K / KC;

    const __nv_bfloat16 *Ahi, *Alo, *Bhi, *Blo;
    if (epi == 0)      { Ahi = g_h_hi;  Alo = g_h_lo;  Bhi = g_w1t_hi;   Blo = g_w1t_lo; }
    else if (epi == 1) { Ahi = g_a_hi;  Alo = g_a_lo;  Bhi = g_w2t_hi;   Blo = g_w2t_lo; }
    else               { Ahi = g_xn_hi; Alo = g_xn_lo; Bhi = g_wqkvt_hi; Blo = g_wqkvt_lo; }

    float acc[2][8][4];
    #pragma unroll
    for (int mi = 0; mi < 2; mi++)
        #pragma unroll
        for (int j = 0; j < 8; j++)
            #pragma unroll
            for (int v = 0; v < 4; v++) acc[mi][j][v] = 0.f;

    const int lrow = tid >> 2, lo16 = (tid & 3) * 16, lk8 = (tid & 3) * 8;
    #define LOAD_CHUNK(kb, s) do {                                              \
        char* _s = (s);                                                         \
        long long ga = (mbase + lrow) * (long long)K + (kb) + lk8;              \
        long long gb = (long long)(nbase + lrow) * K + (kb) + lk8;              \
        uint32_t so = lrow * (SROW * 2) + lo16;                                 \
        *(uint4*)(_s + so)            = *(const uint4*)(Ahi + ga);              \
        *(uint4*)(_s + MATB + so)     = *(const uint4*)(Alo + ga);              \
        *(uint4*)(_s + 2 * MATB + so) = *(const uint4*)(Bhi + gb);              \
        *(uint4*)(_s + 3 * MATB + so) = *(const uint4*)(Blo + gb);              \
        long long ga2 = (mbase + 64 + lrow) * (long long)K + (kb) + lk8;        \
        long long gb2 = (long long)(nbase + 64 + lrow) * K + (kb) + lk8;        \
        uint32_t so2 = (64 + lrow) * (SROW * 2) + lo16;                         \
        *(uint4*)(_s + so2)            = *(const uint4*)(Ahi + ga2);            \
        *(uint4*)(_s + MATB + so2)     = *(const uint4*)(Alo + ga2);            \
        *(uint4*)(_s + 2 * MATB + so2) = *(const uint4*)(Bhi + gb2);            \
        *(uint4*)(_s + 3 * MATB + so2) = *(const uint4*)(Blo + gb2);            \
    } while (0)

    LOAD_CHUNK(0, gsm);
    __syncthreads();

    const int arow = lane & 15;
    const int asel = (lane >> 4) << 3;
    const int br   = lane & 7;
    const int bsel = (lane >> 3) & 3;
    const int bno  = br + ((bsel >> 1) << 3);
    const int bko  = (bsel & 1) << 3;

    for (int c = 0; c < NC; c++) {
        if (c + 1 < NC) LOAD_CHUNK((c + 1) * KC, gsm + ((c + 1) & 1) * GSTAGE);

        const uint32_t sb = smem_u32(gsm + (c & 1) * GSTAGE);
        #pragma unroll
        for (int ks = 0; ks < 2; ks++) {
            uint32_t ahi[2][4], alo[2][4];
            const int acol = ks * 16 + asel;
            #pragma unroll
            for (int mi = 0; mi < 2; mi++) {
                uint32_t aoff = ((wm * 32 + mi * 16 + arow) * SROW + acol) * 2;
                ldm_x4(ahi[mi], sb + aoff);
                ldm_x4(alo[mi], sb + MATB + aoff);
            }
            #pragma unroll
            for (int jj = 0; jj < 4; jj++) {
                uint32_t bhi[4], blo[4];
                uint32_t boff = ((wn * 64 + jj * 16 + bno) * SROW + ks * 16 + bko) * 2;
                ldm_x4(bhi, sb + 2 * MATB + boff);
                ldm_x4(blo, sb + 3 * MATB + boff);
                #pragma unroll
                for (int mi = 0; mi < 2; mi++) {
                    mma16816(acc[mi][2 * jj],     ahi[mi], bhi);
                    mma16816(acc[mi][2 * jj],     ahi[mi], blo);
                    mma16816(acc[mi][2 * jj],     alo[mi], bhi);
                    mma16816(acc[mi][2 * jj + 1], ahi[mi], bhi + 2);
                    mma16816(acc[mi][2 * jj + 1], ahi[mi], blo + 2);
                    mma16816(acc[mi][2 * jj + 1], alo[mi], bhi + 2);
                }
            }
        }
        __syncthreads();
    }

    // ---- epilogue ----
    const int r0 = wm * 32 + (lane >> 2);
    const int cn = wn * 64 + ((lane & 3) << 1);
    #pragma unroll
    for (int mi = 0; mi < 2; mi++) {
        #pragma unroll
        for (int j = 0; j < 8; j++) {
            int col = nbase + cn + j * 8;
            long long rg0 = mbase + r0 + mi * 16;
            long long rg1 = rg0 + 8;
            float* d = acc[mi][j];
            if (epi == 0) {
                float b0 = bias[col], b1 = bias[col + 1];
                float v00 = fmaxf(d[0] + b0, 0.f), v01 = fmaxf(d[1] + b1, 0.f);
                float v10 = fmaxf(d[2] + b0, 0.f), v11 = fmaxf(d[3] + b1, 0.f);
                __nv_bfloat16 h00 = __float2bfloat16(v00), h01 = __float2bfloat16(v01);
                __nv_bfloat16 h10 = __float2bfloat16(v10), h11 = __float2bfloat16(v11);
                *(__nv_bfloat162*)(g_a_hi + rg0 * NTOT + col) = __nv_bfloat162(h00, h01);
                *(__nv_bfloat162*)(g_a_hi + rg1 * NTOT + col) = __nv_bfloat162(h10, h11);
                *(__nv_bfloat162*)(g_a_lo + rg0 * NTOT + col) =
                    __nv_bfloat162(__float2bfloat16(v00 - __bfloat162float(h00)),
                                   __float2bfloat16(v01 - __bfloat162float(h01)));
                *(__nv_bfloat162*)(g_a_lo + rg1 * NTOT + col) =
                    __nv_bfloat162(__float2bfloat16(v10 - __bfloat162float(h10)),
                                   __float2bfloat16(v11 - __bfloat162float(h11)));
            } else if (epi == 1) {
                float b0 = bias[col], b1 = bias[col + 1];
                const float2 rv0 = *(const float2*)(resid + rg0 * NTOT + col);
                const float2 rv1 = *(const float2*)(resid + rg1 * NTOT + col);
                *(float2*)(Of + rg0 * NTOT + col) = make_float2(d[0] + b0 + rv0.x, d[1] + b1 + rv0.y);
                *(float2*)(Of + rg1 * NTOT + col) = make_float2(d[2] + b0 + rv1.x, d[3] + b1 + rv1.y);
            } else {
                float b0 = g_bqkv[col], b1 = g_bqkv[col + 1];
                *(float2*)(g_pkv + rg0 * NTOT + col) = make_float2(d[0] + b0, d[1] + b1);
                *(float2*)(g_pkv + rg1 * NTOT + col) = make_float2(d[2] + b0, d[3] + b1);
            }
        }
    }
}

// ============================================================================
// launch
// ============================================================================
extern "C" void kernel_launch(void* const* d_in, const int* in_sizes, int n_in,
                              void* d_out, int out_size)
{
    (void)in_sizes; (void)n_in; (void)out_size;
    const float* gidx = (const float*)d_in[0];
    const float* lg1  = (const float*)d_in[1];
    const float* lb1  = (const float*)d_in[2];
    const float* lg2  = (const float*)d_in[3];
    const float* lb2  = (const float*)d_in[4];
    const float* Wp   = (const float*)d_in[5];
    const float* bp   = (const float*)d_in[6];
    const float* Wk   = (const float*)d_in[7];
    const float* bk   = (const float*)d_in[8];
    const float* Wv   = (const float*)d_in[9];
    const float* bv   = (const float*)d_in[10];
    const float* W1   = (const float*)d_in[11];
    const float* b1f  = (const float*)d_in[12];
    const float* W2   = (const float*)d_in[13];
    const float* b2f  = (const float*)d_in[14];
    float* out = (float*)d_out;

    cudaFuncSetAttribute(gemm_kernel, cudaFuncAttributeMaxDynamicSharedMemorySize, G_SMEM);
    cudaFuncSetAttribute(attn_kernel, cudaFuncAttributeMaxDynamicSharedMemorySize, AT_SMEM);

    convert_weights<<<4096, 256>>>(W1, W2, Wp, Wk, Wv, bp, bk, bv);
    ln1_kernel<<<MTOT / 8, 256>>>(gidx, lg1, lb1);
    // QKV: [65536 x 512] @ Wqkvt[1536 x 512]^T + bqkv -> g_pkv
    gemm_kernel<<<dim3(MTOT / 128, NQKV / 128), 256, G_SMEM>>>(nullptr, nullptr, nullptr, Cd, NQKV, 2);
    attn_kernel<<<MTOT / 8, 256, AT_SMEM>>>(gidx, lg2, lb2);
    // FFN1: relu -> g_a (hi/lo)
    gemm_kernel<<<dim3(MTOT / 128, FFd / 128), 256, G_SMEM>>>(b1f, nullptr, nullptr, Cd, FFd, 0);
    // FFN2: + b2 + idx -> out
    gemm_kernel<<<dim3(MTOT / 128, Cd / 128), 256, G_SMEM>>>(b2f, gidx, out, FFd, Cd, 1);
}

// round 12
// speedup vs baseline: 5.8409x; 1.3505x over previous
#include <cuda_runtime.h>
#include <cuda_fp16.h>
#include <cstdint>

// ============================================================================
// All-HMMA pipeline, fp16 2-term split:
//   activations: plain fp16 (a = ahi), weights: fp16 hi+lo
//   D = A·Bhi + A·Blo   (fp32 accum; error ~2^-11 relative)
// LN1 -> QKV GEMM -> attention+LN2 -> FFN1 GEMM -> FFN2 GEMM
// B=8192, T=8, C=512, H=8, HS=64, FF=2048.  M_total = 65536 rows.
// ============================================================================

#define Cd 512
#define Td 8
#define Hd 8
#define HSd 64
#define FFd 2048
#define NQKV 1536
#define MTOT 65536

// ---- device scratch ----
__device__ __half g_xn[(size_t)MTOT * Cd];
__device__ float  g_pkv[(size_t)MTOT * NQKV];
__device__ __half g_h[(size_t)MTOT * Cd];
__device__ __half g_a[(size_t)MTOT * FFd];
__device__ __half g_w1t_hi[FFd * Cd];
__device__ __half g_w1t_lo[FFd * Cd];
__device__ __half g_w2t_hi[Cd * FFd];
__device__ __half g_w2t_lo[Cd * FFd];
__device__ __half g_wqkvt_hi[NQKV * Cd];
__device__ __half g_wqkvt_lo[NQKV * Cd];
__device__ float  g_bqkv[NQKV];

__device__ __forceinline__ float wsum(float v) {
    #pragma unroll
    for (int m = 16; m > 0; m >>= 1) v += __shfl_xor_sync(0xffffffffu, v, m);
    return v;
}

// ============================================================================
// Weight conversion: transpose + fp16 hi/lo split
// ============================================================================
__global__ void convert_weights(const float* __restrict__ W1, const float* __restrict__ W2,
                                const float* __restrict__ Wp, const float* __restrict__ Wk,
                                const float* __restrict__ Wv, const float* __restrict__ bp,
                                const float* __restrict__ bk, const float* __restrict__ bv)
{
    int i = blockIdx.x * 256 + threadIdx.x;      // 0 .. 1048575
    {
        int n = i >> 9, k = i & 511;             // W1t [2048 x 512]
        float v = W1[k * FFd + n];
        __half hi = __float2half_rn(v);
        g_w1t_hi[i] = hi;
        g_w1t_lo[i] = __float2half_rn(v - __half2float(hi));
    }
    {
        int n = i >> 11, k = i & 2047;           // W2t [512 x 2048]
        float v = W2[k * Cd + n];
        __half hi = __float2half_rn(v);
        g_w2t_hi[i] = hi;
        g_w2t_lo[i] = __float2half_rn(v - __half2float(hi));
    }
    if (i < NQKV * Cd) {                          // Wqkvt [1536 x 512]
        int n = i >> 9, k = i & 511;
        float v;
        if (n < 512)       v = Wp[(n >> 6) * (Cd * HSd) + k * HSd + (n & 63)];
        else if (n < 1024) { int m = n - 512;  v = Wk[(m >> 6) * (Cd * HSd) + k * HSd + (m & 63)]; }
        else               { int m = n - 1024; v = Wv[(m >> 6) * (Cd * HSd) + k * HSd + (m & 63)]; }
        __half hi = __float2half_rn(v);
        g_wqkvt_hi[i] = hi;
        g_wqkvt_lo[i] = __float2half_rn(v - __half2float(hi));
    }
    if (i < NQKV) {
        float v;
        if (i < 512)       v = bp[i];
        else if (i < 1024) v = bk[i - 512];
        else               v = bv[i - 1024];
        g_bqkv[i] = v;
    }
}

// ============================================================================
// LN1: one warp per row; write x̂ as fp16
// ============================================================================
__global__ void __launch_bounds__(256)
ln1_kernel(const float* __restrict__ gidx,
           const float* __restrict__ lg1, const float* __restrict__ lb1)
{
    const long long row = (long long)blockIdx.x * 8 + (threadIdx.x >> 5);
    const int lane = threadIdx.x & 31;
    const float* xr = gidx + row * Cd;
    float s1 = 0.f, s2 = 0.f;
    #pragma unroll
    for (int c = lane; c < Cd; c += 32) { float v = xr[c]; s1 += v; s2 += v * v; }
    s1 = wsum(s1); s2 = wsum(s2);
    float mean = s1 * (1.0f / Cd);
    float var  = s2 * (1.0f / Cd) - mean * mean;
    float rstd = rsqrtf(var + 1e-5f);
    #pragma unroll
    for (int c = lane; c < Cd; c += 32) {
        float v = (xr[c] - mean) * rstd * lg1[c] + lb1[c];
        g_xn[row * Cd + c] = __float2half_rn(v);
    }
}

// ============================================================================
// Attention + LN2: block = one batch (8 warps = 8 heads, then 8 tokens)
// ============================================================================
#define AT_SPKV 0
#define AT_SATT (8 * 1536)
#define AT_SXR  (AT_SATT + 8 * 512)
#define AT_SW   (AT_SXR + 8 * 512)
#define AT_FLOATS (AT_SW + 8 * 64)
#define AT_SMEM (AT_FLOATS * 4)

__global__ void __launch_bounds__(256, 1)
attn_kernel(const float* __restrict__ gidx,
            const float* __restrict__ lg2, const float* __restrict__ lb2)
{
    extern __shared__ float sm[];
    float* spkv = sm + AT_SPKV;
    float* satt = sm + AT_SATT;
    float* sxr  = sm + AT_SXR;
    float* swei = sm + AT_SW;

    const int tid  = threadIdx.x;
    const int lane = tid & 31;
    const int w    = tid >> 5;
    const long long b = blockIdx.x;

    {
        const float4* src = (const float4*)(g_pkv + b * 8 * NQKV);
        float4* dst = (float4*)spkv;
        #pragma unroll
        for (int i = 0; i < 12; i++) dst[tid + 256 * i] = src[tid + 256 * i];
        const float4* xs = (const float4*)(gidx + b * 8 * Cd);
        float4* xd = (float4*)sxr;
        #pragma unroll
        for (int i = 0; i < 4; i++) xd[tid + 256 * i] = xs[tid + 256 * i];
    }
    __syncthreads();

    {
        const int h = w;
        #pragma unroll
        for (int hf = 0; hf < 2; hf++) {
            int idx = lane + hf * 32;
            int t = idx >> 3, s = idx & 7;
            const float4* pr = (const float4*)(spkv + t * NQKV + h * HSd);
            const float4* kr = (const float4*)(spkv + s * NQKV + 512 + h * HSd);
            float acc = 0.f;
            #pragma unroll
            for (int i = 0; i < 16; i++) {
                float4 a = pr[i], c = kr[i];
                acc += a.x * c.x + a.y * c.y + a.z * c.z + a.w * c.w;
            }
            float logit = acc * 0.125f;
            bool valid  = (s <= t);
            float ml = valid ? logit : -3.0e38f;
            float mx = ml;
            mx = fmaxf(mx, __shfl_xor_sync(0xffffffffu, mx, 1));
            mx = fmaxf(mx, __shfl_xor_sync(0xffffffffu, mx, 2));
            mx = fmaxf(mx, __shfl_xor_sync(0xffffffffu, mx, 4));
            float e = valid ? __expf(logit - mx) : 0.f;
            float smv = e;
            smv += __shfl_xor_sync(0xffffffffu, smv, 1);
            smv += __shfl_xor_sync(0xffffffffu, smv, 2);
            smv += __shfl_xor_sync(0xffffffffu, smv, 4);
            swei[w * 64 + idx] = e / smv;
        }
        __syncwarp();
        const int d0 = lane, d1 = lane + 32;
        #pragma unroll
        for (int t = 0; t < 8; t++) {
            float a0 = 0.f, a1 = 0.f;
            #pragma unroll
            for (int s = 0; s < 8; s++) {
                float wv = swei[w * 64 + t * 8 + s];
                const float* vr = spkv + s * NQKV + 1024 + h * HSd;
                a0 += wv * vr[d0];
                a1 += wv * vr[d1];
            }
            satt[t * Cd + h * HSd + d0] = a0;
            satt[t * Cd + h * HSd + d1] = a1;
        }
    }
    __syncthreads();

    {
        const int t = w;
        const float* ar = satt + t * Cd;
        const float* xr = sxr + t * Cd;
        float s1 = 0.f, s2 = 0.f;
        #pragma unroll
        for (int c = lane; c < Cd; c += 32) { float v = ar[c] + xr[c]; s1 += v; s2 += v * v; }
        s1 = wsum(s1); s2 = wsum(s2);
        float mean = s1 * (1.0f / Cd);
        float var  = s2 * (1.0f / Cd) - mean * mean;
        float rstd = rsqrtf(var + 1e-5f);
        const long long row = b * 8 + t;
        #pragma unroll
        for (int c = lane; c < Cd; c += 32) {
            float v = (ar[c] + xr[c] - mean) * rstd * lg2[c] + lb2[c];
            g_h[row * Cd + c] = __float2half_rn(v);
        }
    }
}

// ============================================================================
// HMMA fp16 2-term GEMM: CTA tile 128x128, K-chunk 32, double-buffered smem.
// smem stage: A | Bhi | Blo  (3 x 10240 bytes)
// epi 0: FFN1  A=g_h,  B=w1t,   relu(d+bias) -> fp16 g_a
// epi 1: FFN2  A=g_a,  B=w2t,   d+bias+resid -> Of (fp32)
// epi 2: QKV   A=g_xn, B=wqkvt, d+g_bqkv     -> g_pkv (fp32)
// ============================================================================

#define KC 32
#define SROW 40
#define MATB (128 * SROW * 2)
#define GSTAGE (3 * MATB)
#define G_SMEM (2 * GSTAGE)

__device__ __forceinline__ uint32_t smem_u32(const void* p) {
    uint32_t a;
    asm("{ .reg .u64 t; cvta.to.shared.u64 t, %1; cvt.u32.u64 %0, t; }" : "=r"(a) : "l"(p));
    return a;
}
__device__ __forceinline__ void ldm_x4(uint32_t* r, uint32_t addr) {
    asm volatile("ldmatrix.sync.aligned.m8n8.x4.shared.b16 {%0,%1,%2,%3}, [%4];"
                 : "=r"(r[0]), "=r"(r[1]), "=r"(r[2]), "=r"(r[3]) : "r"(addr));
}
__device__ __forceinline__ void mma16816(float* c, const uint32_t* a, const uint32_t* b) {
    asm volatile("mma.sync.aligned.m16n8k16.row.col.f32.f16.f16.f32 "
                 "{%0,%1,%2,%3}, {%4,%5,%6,%7}, {%8,%9}, {%0,%1,%2,%3};"
                 : "+f"(c[0]), "+f"(c[1]), "+f"(c[2]), "+f"(c[3])
                 : "r"(a[0]), "r"(a[1]), "r"(a[2]), "r"(a[3]), "r"(b[0]), "r"(b[1]));
}

__global__ void __launch_bounds__(256, 2)
gemm_kernel(const float* __restrict__ bias, const float* __restrict__ resid,
            float* __restrict__ Of, int K, int NTOT, int epi)
{
    extern __shared__ char gsm[];
    const int tid  = threadIdx.x;
    const int lane = tid & 31;
    const int wid  = tid >> 5;
    const int wm   = wid >> 1;
    const int wn   = wid & 1;
    const long long mbase = (long long)blockIdx.x * 128;
    const int nbase = blockIdx.y * 128;
    const int NC = K / KC;

    const __half *A, *Bhi, *Blo;
    if (epi == 0)      { A = g_h;  Bhi = g_w1t_hi;   Blo = g_w1t_lo; }
    else if (epi == 1) { A = g_a;  Bhi = g_w2t_hi;   Blo = g_w2t_lo; }
    else               { A = g_xn; Bhi = g_wqkvt_hi; Blo = g_wqkvt_lo; }

    float acc[2][8][4];
    #pragma unroll
    for (int mi = 0; mi < 2; mi++)
        #pragma unroll
        for (int j = 0; j < 8; j++)
            #pragma unroll
            for (int v = 0; v < 4; v++) acc[mi][j][v] = 0.f;

    const int lrow = tid >> 2, lo16 = (tid & 3) * 16, lk8 = (tid & 3) * 8;
    #define LOAD_CHUNK(kb, s) do {                                              \
        char* _s = (s);                                                         \
        long long ga = (mbase + lrow) * (long long)K + (kb) + lk8;              \
        long long gb = (long long)(nbase + lrow) * K + (kb) + lk8;              \
        uint32_t so = lrow * (SROW * 2) + lo16;                                 \
        *(uint4*)(_s + so)            = *(const uint4*)(A + ga);                \
        *(uint4*)(_s + MATB + so)     = *(const uint4*)(Bhi + gb);              \
        *(uint4*)(_s + 2 * MATB + so) = *(const uint4*)(Blo + gb);              \
        long long ga2 = (mbase + 64 + lrow) * (long long)K + (kb) + lk8;        \
        long long gb2 = (long long)(nbase + 64 + lrow) * K + (kb) + lk8;        \
        uint32_t so2 = (64 + lrow) * (SROW * 2) + lo16;                         \
        *(uint4*)(_s + so2)            = *(const uint4*)(A + ga2);              \
        *(uint4*)(_s + MATB + so2)     = *(const uint4*)(Bhi + gb2);            \
        *(uint4*)(_s + 2 * MATB + so2) = *(const uint4*)(Blo + gb2);            \
    } while (0)

    LOAD_CHUNK(0, gsm);
    __syncthreads();

    const int arow = lane & 15;
    const int asel = (lane >> 4) << 3;
    const int br   = lane & 7;
    const int bsel = (lane >> 3) & 3;
    const int bno  = br + ((bsel >> 1) << 3);
    const int bko  = (bsel & 1) << 3;

    for (int c = 0; c < NC; c++) {
        if (c + 1 < NC) LOAD_CHUNK((c + 1) * KC, gsm + ((c + 1) & 1) * GSTAGE);

        const uint32_t sb = smem_u32(gsm + (c & 1) * GSTAGE);
        #pragma unroll
        for (int ks = 0; ks < 2; ks++) {
            uint32_t a[2][4];
            const int acol = ks * 16 + asel;
            #pragma unroll
            for (int mi = 0; mi < 2; mi++) {
                uint32_t aoff = ((wm * 32 + mi * 16 + arow) * SROW + acol) * 2;
                ldm_x4(a[mi], sb + aoff);
            }
            #pragma unroll
            for (int jj = 0; jj < 4; jj++) {
                uint32_t bhi[4], blo[4];
                uint32_t boff = ((wn * 64 + jj * 16 + bno) * SROW + ks * 16 + bko) * 2;
                ldm_x4(bhi, sb + MATB + boff);
                ldm_x4(blo, sb + 2 * MATB + boff);
                #pragma unroll
                for (int mi = 0; mi < 2; mi++) {
                    mma16816(acc[mi][2 * jj],     a[mi], bhi);
                    mma16816(acc[mi][2 * jj + 1], a[mi], bhi + 2);
                    mma16816(acc[mi][2 * jj],     a[mi], blo);
                    mma16816(acc[mi][2 * jj + 1], a[mi], blo + 2);
                }
            }
        }
        __syncthreads();
    }

    // ---- epilogue ----
    const int r0 = wm * 32 + (lane >> 2);
    const int cn = wn * 64 + ((lane & 3) << 1);
    #pragma unroll
    for (int mi = 0; mi < 2; mi++) {
        #pragma unroll
        for (int j = 0; j < 8; j++) {
            int col = nbase + cn + j * 8;
            long long rg0 = mbase + r0 + mi * 16;
            long long rg1 = rg0 + 8;
            float* d = acc[mi][j];
            if (epi == 0) {
                float b0 = bias[col], b1 = bias[col + 1];
                float v00 = fmaxf(d[0] + b0, 0.f), v01 = fmaxf(d[1] + b1, 0.f);
                float v10 = fmaxf(d[2] + b0, 0.f), v11 = fmaxf(d[3] + b1, 0.f);
                *(__half2*)(g_a + rg0 * NTOT + col) = __floats2half2_rn(v00, v01);
                *(__half2*)(g_a + rg1 * NTOT + col) = __floats2half2_rn(v10, v11);
            } else if (epi == 1) {
                float b0 = bias[col], b1 = bias[col + 1];
                const float2 rv0 = *(const float2*)(resid + rg0 * NTOT + col);
                const float2 rv1 = *(const float2*)(resid + rg1 * NTOT + col);
                *(float2*)(Of + rg0 * NTOT + col) = make_float2(d[0] + b0 + rv0.x, d[1] + b1 + rv0.y);
                *(float2*)(Of + rg1 * NTOT + col) = make_float2(d[2] + b0 + rv1.x, d[3] + b1 + rv1.y);
            } else {
                float b0 = g_bqkv[col], b1 = g_bqkv[col + 1];
                *(float2*)(g_pkv + rg0 * NTOT + col) = make_float2(d[0] + b0, d[1] + b1);
                *(float2*)(g_pkv + rg1 * NTOT + col) = make_float2(d[2] + b0, d[3] + b1);
            }
        }
    }
}

// ============================================================================
// launch
// ============================================================================
extern "C" void kernel_launch(void* const* d_in, const int* in_sizes, int n_in,
                              void* d_out, int out_size)
{
    (void)in_sizes; (void)n_in; (void)out_size;
    const float* gidx = (const float*)d_in[0];
    const float* lg1  = (const float*)d_in[1];
    const float* lb1  = (const float*)d_in[2];
    const float* lg2  = (const float*)d_in[3];
    const float* lb2  = (const float*)d_in[4];
    const float* Wp   = (const float*)d_in[5];
    const float* bp   = (const float*)d_in[6];
    const float* Wk   = (const float*)d_in[7];
    const float* bk   = (const float*)d_in[8];
    const float* Wv   = (const float*)d_in[9];
    const float* bv   = (const float*)d_in[10];
    const float* W1   = (const float*)d_in[11];
    const float* b1f  = (const float*)d_in[12];
    const float* W2   = (const float*)d_in[13];
    const float* b2f  = (const float*)d_in[14];
    float* out = (float*)d_out;

    cudaFuncSetAttribute(gemm_kernel, cudaFuncAttributeMaxDynamicSharedMemorySize, G_SMEM);
    cudaFuncSetAttribute(attn_kernel, cudaFuncAttributeMaxDynamicSharedMemorySize, AT_SMEM);

    convert_weights<<<4096, 256>>>(W1, W2, Wp, Wk, Wv, bp, bk, bv);
    ln1_kernel<<<MTOT / 8, 256>>>(gidx, lg1, lb1);
    // QKV: [65536 x 512] @ Wqkvt[1536 x 512]^T + bqkv -> g_pkv
    gemm_kernel<<<dim3(MTOT / 128, NQKV / 128), 256, G_SMEM>>>(nullptr, nullptr, nullptr, Cd, NQKV, 2);
    attn_kernel<<<MTOT / 8, 256, AT_SMEM>>>(gidx, lg2, lb2);
    // FFN1: relu -> g_a (fp16)
    gemm_kernel<<<dim3(MTOT / 128, FFd / 128), 256, G_SMEM>>>(b1f, nullptr, nullptr, Cd, FFd, 0);
    // FFN2: + b2 + idx -> out
    gemm_kernel<<<dim3(MTOT / 128, Cd / 128), 256, G_SMEM>>>(b2f, gidx, out, FFd, Cd, 1);
}

// round 13
// speedup vs baseline: 7.1337x; 1.2213x over previous
#include <cuda_runtime.h>
#include <cuda_fp16.h>
#include <cstdint>

// ============================================================================
// All-HMMA pipeline, fp16 2-term split + cp.async GEMM pipeline + fp16 pkv.
//   activations: plain fp16, weights: fp16 hi+lo; D = A·Bhi + A·Blo (fp32 acc)
// LN1 -> QKV GEMM -> attention+LN2 -> FFN1 GEMM -> FFN2 GEMM
// B=8192, T=8, C=512, H=8, HS=64, FF=2048.  M_total = 65536 rows.
// ============================================================================

#define Cd 512
#define Td 8
#define Hd 8
#define HSd 64
#define FFd 2048
#define NQKV 1536
#define MTOT 65536

// ---- device scratch ----
__device__ __half g_xn[(size_t)MTOT * Cd];
__device__ __half g_pkv[(size_t)MTOT * NQKV];
__device__ __half g_h[(size_t)MTOT * Cd];
__device__ __half g_a[(size_t)MTOT * FFd];
__device__ __half g_w1t_hi[FFd * Cd];
__device__ __half g_w1t_lo[FFd * Cd];
__device__ __half g_w2t_hi[Cd * FFd];
__device__ __half g_w2t_lo[Cd * FFd];
__device__ __half g_wqkvt_hi[NQKV * Cd];
__device__ __half g_wqkvt_lo[NQKV * Cd];
__device__ float  g_bqkv[NQKV];

__device__ __forceinline__ float wsum(float v) {
    #pragma unroll
    for (int m = 16; m > 0; m >>= 1) v += __shfl_xor_sync(0xffffffffu, v, m);
    return v;
}

// ============================================================================
// Weight conversion: transpose + fp16 hi/lo split
// ============================================================================
__global__ void convert_weights(const float* __restrict__ W1, const float* __restrict__ W2,
                                const float* __restrict__ Wp, const float* __restrict__ Wk,
                                const float* __restrict__ Wv, const float* __restrict__ bp,
                                const float* __restrict__ bk, const float* __restrict__ bv)
{
    int i = blockIdx.x * 256 + threadIdx.x;      // 0 .. 1048575
    {
        int n = i >> 9, k = i & 511;             // W1t [2048 x 512]
        float v = W1[k * FFd + n];
        __half hi = __float2half_rn(v);
        g_w1t_hi[i] = hi;
        g_w1t_lo[i] = __float2half_rn(v - __half2float(hi));
    }
    {
        int n = i >> 11, k = i & 2047;           // W2t [512 x 2048]
        float v = W2[k * Cd + n];
        __half hi = __float2half_rn(v);
        g_w2t_hi[i] = hi;
        g_w2t_lo[i] = __float2half_rn(v - __half2float(hi));
    }
    if (i < NQKV * Cd) {                          // Wqkvt [1536 x 512]
        int n = i >> 9, k = i & 511;
        float v;
        if (n < 512)       v = Wp[(n >> 6) * (Cd * HSd) + k * HSd + (n & 63)];
        else if (n < 1024) { int m = n - 512;  v = Wk[(m >> 6) * (Cd * HSd) + k * HSd + (m & 63)]; }
        else               { int m = n - 1024; v = Wv[(m >> 6) * (Cd * HSd) + k * HSd + (m & 63)]; }
        __half hi = __float2half_rn(v);
        g_wqkvt_hi[i] = hi;
        g_wqkvt_lo[i] = __float2half_rn(v - __half2float(hi));
    }
    if (i < NQKV) {
        float v;
        if (i < 512)       v = bp[i];
        else if (i < 1024) v = bk[i - 512];
        else               v = bv[i - 1024];
        g_bqkv[i] = v;
    }
}

// ============================================================================
// LN1: one warp per row; write x̂ as fp16
// ============================================================================
__global__ void __launch_bounds__(256)
ln1_kernel(const float* __restrict__ gidx,
           const float* __restrict__ lg1, const float* __restrict__ lb1)
{
    const long long row = (long long)blockIdx.x * 8 + (threadIdx.x >> 5);
    const int lane = threadIdx.x & 31;
    const float* xr = gidx + row * Cd;
    float s1 = 0.f, s2 = 0.f;
    #pragma unroll
    for (int c = lane; c < Cd; c += 32) { float v = xr[c]; s1 += v; s2 += v * v; }
    s1 = wsum(s1); s2 = wsum(s2);
    float mean = s1 * (1.0f / Cd);
    float var  = s2 * (1.0f / Cd) - mean * mean;
    float rstd = rsqrtf(var + 1e-5f);
    #pragma unroll
    for (int c = lane; c < Cd; c += 32) {
        float v = (xr[c] - mean) * rstd * lg1[c] + lb1[c];
        g_xn[row * Cd + c] = __float2half_rn(v);
    }
}

// ============================================================================
// Attention + LN2: block = one batch (8 warps = 8 heads, then 8 tokens)
// smem: spkv (fp16, 8x1536) | satt (f32 8x512) | sxr (f32 8x512) | swei (8x64)
// ============================================================================
#define AT_PKV_B   (8 * NQKV * 2)                       // 24576
#define AT_SATT_B  AT_PKV_B                             // float region starts
#define AT_SXR_B   (AT_SATT_B + 8 * Cd * 4)
#define AT_SW_B    (AT_SXR_B + 8 * Cd * 4)
#define AT_SMEM    (AT_SW_B + 8 * 64 * 4)               // 59392

__global__ void __launch_bounds__(256, 3)
attn_kernel(const float* __restrict__ gidx,
            const float* __restrict__ lg2, const float* __restrict__ lb2)
{
    extern __shared__ char smc[];
    __half* spkv = (__half*)smc;
    float*  satt = (float*)(smc + AT_SATT_B);
    float*  sxr  = (float*)(smc + AT_SXR_B);
    float*  swei = (float*)(smc + AT_SW_B);

    const int tid  = threadIdx.x;
    const int lane = tid & 31;
    const int w    = tid >> 5;
    const long long b = blockIdx.x;

    {
        const uint4* src = (const uint4*)(g_pkv + b * 8 * NQKV);   // 1536 uint4
        uint4* dst = (uint4*)spkv;
        #pragma unroll
        for (int i = 0; i < 6; i++) dst[tid + 256 * i] = src[tid + 256 * i];
        const float4* xs = (const float4*)(gidx + b * 8 * Cd);
        float4* xd = (float4*)sxr;
        #pragma unroll
        for (int i = 0; i < 4; i++) xd[tid + 256 * i] = xs[tid + 256 * i];
    }
    __syncthreads();

    {
        const int h = w;
        #pragma unroll
        for (int hf = 0; hf < 2; hf++) {
            int idx = lane + hf * 32;
            int t = idx >> 3, s = idx & 7;
            const __half2* pr = (const __half2*)(spkv + t * NQKV + h * HSd);
            const __half2* kr = (const __half2*)(spkv + s * NQKV + 512 + h * HSd);
            float acc = 0.f;
            #pragma unroll
            for (int i = 0; i < 32; i++) {
                float2 a = __half22float2(pr[i]);
                float2 c = __half22float2(kr[i]);
                acc += a.x * c.x + a.y * c.y;
            }
            float logit = acc * 0.125f;
            bool valid  = (s <= t);
            float ml = valid ? logit : -3.0e38f;
            float mx = ml;
            mx = fmaxf(mx, __shfl_xor_sync(0xffffffffu, mx, 1));
            mx = fmaxf(mx, __shfl_xor_sync(0xffffffffu, mx, 2));
            mx = fmaxf(mx, __shfl_xor_sync(0xffffffffu, mx, 4));
            float e = valid ? __expf(logit - mx) : 0.f;
            float smv = e;
            smv += __shfl_xor_sync(0xffffffffu, smv, 1);
            smv += __shfl_xor_sync(0xffffffffu, smv, 2);
            smv += __shfl_xor_sync(0xffffffffu, smv, 4);
            swei[w * 64 + idx] = e / smv;
        }
        __syncwarp();
        const int d0 = lane, d1 = lane + 32;
        #pragma unroll
        for (int t = 0; t < 8; t++) {
            float a0 = 0.f, a1 = 0.f;
            #pragma unroll
            for (int s = 0; s < 8; s++) {
                float wv = swei[w * 64 + t * 8 + s];
                const __half* vr = spkv + s * NQKV + 1024 + h * HSd;
                a0 += wv * __half2float(vr[d0]);
                a1 += wv * __half2float(vr[d1]);
            }
            satt[t * Cd + h * HSd + d0] = a0;
            satt[t * Cd + h * HSd + d1] = a1;
        }
    }
    __syncthreads();

    {
        const int t = w;
        const float* ar = satt + t * Cd;
        const float* xr = sxr + t * Cd;
        float s1 = 0.f, s2 = 0.f;
        #pragma unroll
        for (int c = lane; c < Cd; c += 32) { float v = ar[c] + xr[c]; s1 += v; s2 += v * v; }
        s1 = wsum(s1); s2 = wsum(s2);
        float mean = s1 * (1.0f / Cd);
        float var  = s2 * (1.0f / Cd) - mean * mean;
        float rstd = rsqrtf(var + 1e-5f);
        const long long row = b * 8 + t;
        #pragma unroll
        for (int c = lane; c < Cd; c += 32) {
            float v = (ar[c] + xr[c] - mean) * rstd * lg2[c] + lb2[c];
            g_h[row * Cd + c] = __float2half_rn(v);
        }
    }
}

// ============================================================================
// HMMA fp16 2-term GEMM, cp.async double-buffered.
// smem stage: A | Bhi | Blo  (3 x 10240 bytes)
// epi 0: FFN1  A=g_h,  B=w1t,   relu(d+bias) -> fp16 g_a
// epi 1: FFN2  A=g_a,  B=w2t,   d+bias+resid -> Of (fp32)
// epi 2: QKV   A=g_xn, B=wqkvt, d+g_bqkv     -> fp16 g_pkv
// ============================================================================

#define KC 32
#define SROW 40
#define MATB (128 * SROW * 2)
#define GSTAGE (3 * MATB)
#define G_SMEM (2 * GSTAGE)

__device__ __forceinline__ uint32_t smem_u32(const void* p) {
    uint32_t a;
    asm("{ .reg .u64 t; cvta.to.shared.u64 t, %1; cvt.u32.u64 %0, t; }" : "=r"(a) : "l"(p));
    return a;
}
__device__ __forceinline__ void cp16(uint32_t dst, const void* src) {
    asm volatile("cp.async.cg.shared.global [%0], [%1], 16;" :: "r"(dst), "l"(src));
}
__device__ __forceinline__ void cp_commit() {
    asm volatile("cp.async.commit_group;" ::: "memory");
}
__device__ __forceinline__ void cp_wait0() {
    asm volatile("cp.async.wait_group 0;" ::: "memory");
}
__device__ __forceinline__ void ldm_x4(uint32_t* r, uint32_t addr) {
    asm volatile("ldmatrix.sync.aligned.m8n8.x4.shared.b16 {%0,%1,%2,%3}, [%4];"
                 : "=r"(r[0]), "=r"(r[1]), "=r"(r[2]), "=r"(r[3]) : "r"(addr));
}
__device__ __forceinline__ void mma16816(float* c, const uint32_t* a, const uint32_t* b) {
    asm volatile("mma.sync.aligned.m16n8k16.row.col.f32.f16.f16.f32 "
                 "{%0,%1,%2,%3}, {%4,%5,%6,%7}, {%8,%9}, {%0,%1,%2,%3};"
                 : "+f"(c[0]), "+f"(c[1]), "+f"(c[2]), "+f"(c[3])
                 : "r"(a[0]), "r"(a[1]), "r"(a[2]), "r"(a[3]), "r"(b[0]), "r"(b[1]));
}

__global__ void __launch_bounds__(256, 2)
gemm_kernel(const float* __restrict__ bias, const float* __restrict__ resid,
            float* __restrict__ Of, int K, int NTOT, int epi)
{
    extern __shared__ char gsm[];
    const uint32_t sbase = smem_u32(gsm);
    const int tid  = threadIdx.x;
    const int lane = tid & 31;
    const int wid  = tid >> 5;
    const int wm   = wid >> 1;
    const int wn   = wid & 1;
    const long long mbase = (long long)blockIdx.x * 128;
    const int nbase = blockIdx.y * 128;
    const int NC = K / KC;

    const __half *A, *Bhi, *Blo;
    if (epi == 0)      { A = g_h;  Bhi = g_w1t_hi;   Blo = g_w1t_lo; }
    else if (epi == 1) { A = g_a;  Bhi = g_w2t_hi;   Blo = g_w2t_lo; }
    else               { A = g_xn; Bhi = g_wqkvt_hi; Blo = g_wqkvt_lo; }

    float acc[2][8][4];
    #pragma unroll
    for (int mi = 0; mi < 2; mi++)
        #pragma unroll
        for (int j = 0; j < 8; j++)
            #pragma unroll
            for (int v = 0; v < 4; v++) acc[mi][j][v] = 0.f;

    const int lrow = tid >> 2, lo16 = (tid & 3) * 16, lk8 = (tid & 3) * 8;
    #define LOAD_CHUNK_ASYNC(kb, soff) do {                                     \
        uint32_t _sb = sbase + (soff);                                          \
        long long ga = (mbase + lrow) * (long long)K + (kb) + lk8;              \
        long long gb = (long long)(nbase + lrow) * K + (kb) + lk8;              \
        uint32_t so = lrow * (SROW * 2) + lo16;                                 \
        cp16(_sb + so,            A + ga);                                      \
        cp16(_sb + MATB + so,     Bhi + gb);                                    \
        cp16(_sb + 2 * MATB + so, Blo + gb);                                    \
        long long ga2 = (mbase + 64 + lrow) * (long long)K + (kb) + lk8;        \
        long long gb2 = (long long)(nbase + 64 + lrow) * K + (kb) + lk8;        \
        uint32_t so2 = (64 + lrow) * (SROW * 2) + lo16;                         \
        cp16(_sb + so2,            A + ga2);                                    \
        cp16(_sb + MATB + so2,     Bhi + gb2);                                  \
        cp16(_sb + 2 * MATB + so2, Blo + gb2);                                  \
    } while (0)

    LOAD_CHUNK_ASYNC(0, 0);
    cp_commit();
    cp_wait0();
    __syncthreads();

    const int arow = lane & 15;
    const int asel = (lane >> 4) << 3;
    const int br   = lane & 7;
    const int bsel = (lane >> 3) & 3;
    const int bno  = br + ((bsel >> 1) << 3);
    const int bko  = (bsel & 1) << 3;

    for (int c = 0; c < NC; c++) {
        if (c + 1 < NC) {
            LOAD_CHUNK_ASYNC((c + 1) * KC, ((c + 1) & 1) * GSTAGE);
            cp_commit();
        }

        const uint32_t sb = sbase + (c & 1) * GSTAGE;
        #pragma unroll
        for (int ks = 0; ks < 2; ks++) {
            uint32_t a[2][4];
            const int acol = ks * 16 + asel;
            #pragma unroll
            for (int mi = 0; mi < 2; mi++) {
                uint32_t aoff = ((wm * 32 + mi * 16 + arow) * SROW + acol) * 2;
                ldm_x4(a[mi], sb + aoff);
            }
            #pragma unroll
            for (int jj = 0; jj < 4; jj++) {
                uint32_t bhi[4], blo[4];
                uint32_t boff = ((wn * 64 + jj * 16 + bno) * SROW + ks * 16 + bko) * 2;
                ldm_x4(bhi, sb + MATB + boff);
                ldm_x4(blo, sb + 2 * MATB + boff);
                #pragma unroll
                for (int mi = 0; mi < 2; mi++) {
                    mma16816(acc[mi][2 * jj],     a[mi], bhi);
                    mma16816(acc[mi][2 * jj + 1], a[mi], bhi + 2);
                    mma16816(acc[mi][2 * jj],     a[mi], blo);
                    mma16816(acc[mi][2 * jj + 1], a[mi], blo + 2);
                }
            }
        }
        cp_wait0();
        __syncthreads();
    }

    // ---- epilogue ----
    const int r0 = wm * 32 + (lane >> 2);
    const int cn = wn * 64 + ((lane & 3) << 1);
    #pragma unroll
    for (int mi = 0; mi < 2; mi++) {
        #pragma unroll
        for (int j = 0; j < 8; j++) {
            int col = nbase + cn + j * 8;
            long long rg0 = mbase + r0 + mi * 16;
            long long rg1 = rg0 + 8;
            float* d = acc[mi][j];
            if (epi == 0) {
                float b0 = bias[col], b1 = bias[col + 1];
                float v00 = fmaxf(d[0] + b0, 0.f), v01 = fmaxf(d[1] + b1, 0.f);
                float v10 = fmaxf(d[2] + b0, 0.f), v11 = fmaxf(d[3] + b1, 0.f);
                *(__half2*)(g_a + rg0 * NTOT + col) = __floats2half2_rn(v00, v01);
                *(__half2*)(g_a + rg1 * NTOT + col) = __floats2half2_rn(v10, v11);
            } else if (epi == 1) {
                float b0 = bias[col], b1 = bias[col + 1];
                const float2 rv0 = *(const float2*)(resid + rg0 * NTOT + col);
                const float2 rv1 = *(const float2*)(resid + rg1 * NTOT + col);
                *(float2*)(Of + rg0 * NTOT + col) = make_float2(d[0] + b0 + rv0.x, d[1] + b1 + rv0.y);
                *(float2*)(Of + rg1 * NTOT + col) = make_float2(d[2] + b0 + rv1.x, d[3] + b1 + rv1.y);
            } else {
                float b0 = g_bqkv[col], b1 = g_bqkv[col + 1];
                *(__half2*)(g_pkv + rg0 * NTOT + col) = __floats2half2_rn(d[0] + b0, d[1] + b1);
                *(__half2*)(g_pkv + rg1 * NTOT + col) = __floats2half2_rn(d[2] + b0, d[3] + b1);
            }
        }
    }
}

// ============================================================================
// launch
// ============================================================================
extern "C" void kernel_launch(void* const* d_in, const int* in_sizes, int n_in,
                              void* d_out, int out_size)
{
    (void)in_sizes; (void)n_in; (void)out_size;
    const float* gidx = (const float*)d_in[0];
    const float* lg1  = (const float*)d_in[1];
    const float* lb1  = (const float*)d_in[2];
    const float* lg2  = (const float*)d_in[3];
    const float* lb2  = (const float*)d_in[4];
    const float* Wp   = (const float*)d_in[5];
    const float* bp   = (const float*)d_in[6];
    const float* Wk   = (const float*)d_in[7];
    const float* bk   = (const float*)d_in[8];
    const float* Wv   = (const float*)d_in[9];
    const float* bv   = (const float*)d_in[10];
    const float* W1   = (const float*)d_in[11];
    const float* b1f  = (const float*)d_in[12];
    const float* W2   = (const float*)d_in[13];
    const float* b2f  = (const float*)d_in[14];
    float* out = (float*)d_out;

    cudaFuncSetAttribute(gemm_kernel, cudaFuncAttributeMaxDynamicSharedMemorySize, G_SMEM);
    cudaFuncSetAttribute(attn_kernel, cudaFuncAttributeMaxDynamicSharedMemorySize, AT_SMEM);

    convert_weights<<<4096, 256>>>(W1, W2, Wp, Wk, Wv, bp, bk, bv);
    ln1_kernel<<<MTOT / 8, 256>>>(gidx, lg1, lb1);
    // QKV: [65536 x 512] @ Wqkvt[1536 x 512]^T + bqkv -> fp16 g_pkv
    gemm_kernel<<<dim3(MTOT / 128, NQKV / 128), 256, G_SMEM>>>(nullptr, nullptr, nullptr, Cd, NQKV, 2);
    attn_kernel<<<MTOT / 8, 256, AT_SMEM>>>(gidx, lg2, lb2);
    // FFN1: relu -> g_a (fp16)
    gemm_kernel<<<dim3(MTOT / 128, FFd / 128), 256, G_SMEM>>>(b1f, nullptr, nullptr, Cd, FFd, 0);
    // FFN2: + b2 + idx -> out
    gemm_kernel<<<dim3(MTOT / 128, Cd / 128), 256, G_SMEM>>>(b2f, gidx, out, FFd, Cd, 1);
}

// round 15
// speedup vs baseline: 10.6062x; 1.4868x over previous
#include <cuda_runtime.h>
#include <cuda_fp16.h>
#include <cstdint>

// ============================================================================
// All-HMMA pipeline, plain fp16 GEMMs (single term), cp.async double-buffered.
// LN1 -> QKV GEMM -> attention+LN2 -> FFN1 GEMM -> FFN2 GEMM
// B=8192, T=8, C=512, H=8, HS=64, FF=2048.  M_total = 65536 rows.
// ============================================================================

#define Cd 512
#define Td 8
#define Hd 8
#define HSd 64
#define FFd 2048
#define NQKV 1536
#define MTOT 65536

// ---- device scratch ----
__device__ __half g_xn[(size_t)MTOT * Cd];
__device__ __half g_pkv[(size_t)MTOT * NQKV];
__device__ __half g_h[(size_t)MTOT * Cd];
__device__ __half g_a[(size_t)MTOT * FFd];
__device__ __half g_w1t[FFd * Cd];
__device__ __half g_w2t[Cd * FFd];
__device__ __half g_wqkvt[NQKV * Cd];
__device__ float  g_bqkv[NQKV];

__device__ __forceinline__ float wsum(float v) {
    #pragma unroll
    for (int m = 16; m > 0; m >>= 1) v += __shfl_xor_sync(0xffffffffu, v, m);
    return v;
}

// ============================================================================
// Weight conversion: transpose + fp16
// ============================================================================
__global__ void convert_weights(const float* __restrict__ W1, const float* __restrict__ W2,
                                const float* __restrict__ Wp, const float* __restrict__ Wk,
                                const float* __restrict__ Wv, const float* __restrict__ bp,
                                const float* __restrict__ bk, const float* __restrict__ bv)
{
    int i = blockIdx.x * 256 + threadIdx.x;      // 0 .. 1048575
    {
        int n = i >> 9, k = i & 511;             // W1t [2048 x 512]
        g_w1t[i] = __float2half_rn(W1[k * FFd + n]);
    }
    {
        int n = i >> 11, k = i & 2047;           // W2t [512 x 2048]
        g_w2t[i] = __float2half_rn(W2[k * Cd + n]);
    }
    if (i < NQKV * Cd) {                          // Wqkvt [1536 x 512]
        int n = i >> 9, k = i & 511;
        float v;
        if (n < 512)       v = Wp[(n >> 6) * (Cd * HSd) + k * HSd + (n & 63)];
        else if (n < 1024) { int m = n - 512;  v = Wk[(m >> 6) * (Cd * HSd) + k * HSd + (m & 63)]; }
        else               { int m = n - 1024; v = Wv[(m >> 6) * (Cd * HSd) + k * HSd + (m & 63)]; }
        g_wqkvt[i] = __float2half_rn(v);
    }
    if (i < NQKV) {
        float v;
        if (i < 512)       v = bp[i];
        else if (i < 1024) v = bk[i - 512];
        else               v = bv[i - 1024];
        g_bqkv[i] = v;
    }
}

// ============================================================================
// LN1: one warp per row; write x̂ as fp16
// ============================================================================
__global__ void __launch_bounds__(256)
ln1_kernel(const float* __restrict__ gidx,
           const float* __restrict__ lg1, const float* __restrict__ lb1)
{
    const long long row = (long long)blockIdx.x * 8 + (threadIdx.x >> 5);
    const int lane = threadIdx.x & 31;
    const float* xr = gidx + row * Cd;
    float s1 = 0.f, s2 = 0.f;
    #pragma unroll
    for (int c = lane; c < Cd; c += 32) { float v = xr[c]; s1 += v; s2 += v * v; }
    s1 = wsum(s1); s2 = wsum(s2);
    float mean = s1 * (1.0f / Cd);
    float var  = s2 * (1.0f / Cd) - mean * mean;
    float rstd = rsqrtf(var + 1e-5f);
    #pragma unroll
    for (int c = lane; c < Cd; c += 32) {
        float v = (xr[c] - mean) * rstd * lg1[c] + lb1[c];
        g_xn[row * Cd + c] = __float2half_rn(v);
    }
}

// ============================================================================
// Attention + LN2: block = one batch (8 warps = 8 heads, then 8 tokens)
// ============================================================================
#define AT_PKV_B   (8 * NQKV * 2)                       // 24576
#define AT_SATT_B  AT_PKV_B
#define AT_SXR_B   (AT_SATT_B + 8 * Cd * 4)
#define AT_SW_B    (AT_SXR_B + 8 * Cd * 4)
#define AT_SMEM    (AT_SW_B + 8 * 64 * 4)               // 59392

__global__ void __launch_bounds__(256, 3)
attn_kernel(const float* __restrict__ gidx,
            const float* __restrict__ lg2, const float* __restrict__ lb2)
{
    extern __shared__ char smc[];
    __half* spkv = (__half*)smc;
    float*  satt = (float*)(smc + AT_SATT_B);
    float*  sxr  = (float*)(smc + AT_SXR_B);
    float*  swei = (float*)(smc + AT_SW_B);

    const int tid  = threadIdx.x;
    const int lane = tid & 31;
    const int w    = tid >> 5;
    const long long b = blockIdx.x;

    {
        const uint4* src = (const uint4*)(g_pkv + b * 8 * NQKV);
        uint4* dst = (uint4*)spkv;
        #pragma unroll
        for (int i = 0; i < 6; i++) dst[tid + 256 * i] = src[tid + 256 * i];
        const float4* xs = (const float4*)(gidx + b * 8 * Cd);
        float4* xd = (float4*)sxr;
        #pragma unroll
        for (int i = 0; i < 4; i++) xd[tid + 256 * i] = xs[tid + 256 * i];
    }
    __syncthreads();

    {
        const int h = w;
        #pragma unroll
        for (int hf = 0; hf < 2; hf++) {
            int idx = lane + hf * 32;
            int t = idx >> 3, s = idx & 7;
            const __half2* pr = (const __half2*)(spkv + t * NQKV + h * HSd);
            const __half2* kr = (const __half2*)(spkv + s * NQKV + 512 + h * HSd);
            float acc = 0.f;
            #pragma unroll
            for (int i = 0; i < 32; i++) {
                float2 a = __half22float2(pr[i]);
                float2 c = __half22float2(kr[i]);
                acc += a.x * c.x + a.y * c.y;
            }
            float logit = acc * 0.125f;
            bool valid  = (s <= t);
            float ml = valid ? logit : -3.0e38f;
            float mx = ml;
            mx = fmaxf(mx, __shfl_xor_sync(0xffffffffu, mx, 1));
            mx = fmaxf(mx, __shfl_xor_sync(0xffffffffu, mx, 2));
            mx = fmaxf(mx, __shfl_xor_sync(0xffffffffu, mx, 4));
            float e = valid ? __expf(logit - mx) : 0.f;
            float smv = e;
            smv += __shfl_xor_sync(0xffffffffu, smv, 1);
            smv += __shfl_xor_sync(0xffffffffu, smv, 2);
            smv += __shfl_xor_sync(0xffffffffu, smv, 4);
            swei[w * 64 + idx] = e / smv;
        }
        __syncwarp();
        const int d0 = lane, d1 = lane + 32;
        #pragma unroll
        for (int t = 0; t < 8; t++) {
            float a0 = 0.f, a1 = 0.f;
            #pragma unroll
            for (int s = 0; s < 8; s++) {
                float wv = swei[w * 64 + t * 8 + s];
                const __half* vr = spkv + s * NQKV + 1024 + h * HSd;
                a0 += wv * __half2float(vr[d0]);
                a1 += wv * __half2float(vr[d1]);
            }
            satt[t * Cd + h * HSd + d0] = a0;
            satt[t * Cd + h * HSd + d1] = a1;
        }
    }
    __syncthreads();

    {
        const int t = w;
        const float* ar = satt + t * Cd;
        const float* xr = sxr + t * Cd;
        float s1 = 0.f, s2 = 0.f;
        #pragma unroll
        for (int c = lane; c < Cd; c += 32) { float v = ar[c] + xr[c]; s1 += v; s2 += v * v; }
        s1 = wsum(s1); s2 = wsum(s2);
        float mean = s1 * (1.0f / Cd);
        float var  = s2 * (1.0f / Cd) - mean * mean;
        float rstd = rsqrtf(var + 1e-5f);
        const long long row = b * 8 + t;
        #pragma unroll
        for (int c = lane; c < Cd; c += 32) {
            float v = (ar[c] + xr[c] - mean) * rstd * lg2[c] + lb2[c];
            g_h[row * Cd + c] = __float2half_rn(v);
        }
    }
}

// ============================================================================
// HMMA fp16 GEMM, cp.async double-buffered.  smem stage: A | B  (2 x 10240 B)
// epi 0: FFN1  A=g_h,  B=w1t,   relu(d+bias) -> fp16 g_a
// epi 1: FFN2  A=g_a,  B=w2t,   d+bias+resid -> Of (fp32)
// epi 2: QKV   A=g_xn, B=wqkvt, d+g_bqkv     -> fp16 g_pkv
// ============================================================================

#define KC 32
#define SROW 40
#define MATB (128 * SROW * 2)
#define GSTAGE (2 * MATB)
#define G_SMEM (2 * GSTAGE)

__device__ __forceinline__ uint32_t smem_u32(const void* p) {
    uint32_t a;
    asm("{ .reg .u64 t; cvta.to.shared.u64 t, %1; cvt.u32.u64 %0, t; }" : "=r"(a) : "l"(p));
    return a;
}
__device__ __forceinline__ void cp16(uint32_t dst, const void* src) {
    asm volatile("cp.async.cg.shared.global [%0], [%1], 16;" :: "r"(dst), "l"(src));
}
__device__ __forceinline__ void cp_commit() {
    asm volatile("cp.async.commit_group;" ::: "memory");
}
__device__ __forceinline__ void cp_wait0() {
    asm volatile("cp.async.wait_group 0;" ::: "memory");
}
__device__ __forceinline__ void ldm_x4(uint32_t* r, uint32_t addr) {
    asm volatile("ldmatrix.sync.aligned.m8n8.x4.shared.b16 {%0,%1,%2,%3}, [%4];"
                 : "=r"(r[0]), "=r"(r[1]), "=r"(r[2]), "=r"(r[3]) : "r"(addr));
}
__device__ __forceinline__ void mma16816(float* c, const uint32_t* a, const uint32_t* b) {
    asm volatile("mma.sync.aligned.m16n8k16.row.col.f32.f16.f16.f32 "
                 "{%0,%1,%2,%3}, {%4,%5,%6,%7}, {%8,%9}, {%0,%1,%2,%3};"
                 : "+f"(c[0]), "+f"(c[1]), "+f"(c[2]), "+f"(c[3])
                 : "r"(a[0]), "r"(a[1]), "r"(a[2]), "r"(a[3]), "r"(b[0]), "r"(b[1]));
}

__global__ void __launch_bounds__(256, 2)
gemm_kernel(const float* __restrict__ bias, const float* __restrict__ resid,
            float* __restrict__ Of, int K, int NTOT, int epi)
{
    extern __shared__ char gsm[];
    const uint32_t sbase = smem_u32(gsm);
    const int tid  = threadIdx.x;
    const int lane = tid & 31;
    const int wid  = tid >> 5;
    const int wm   = wid >> 1;
    const int wn   = wid & 1;
    const long long mbase = (long long)blockIdx.x * 128;
    const int nbase = blockIdx.y * 128;
    const int NC = K / KC;

    const __half *A, *B;
    if (epi == 0)      { A = g_h;  B = g_w1t; }
    else if (epi == 1) { A = g_a;  B = g_w2t; }
    else               { A = g_xn; B = g_wqkvt; }

    float acc[2][8][4];
    #pragma unroll
    for (int mi = 0; mi < 2; mi++)
        #pragma unroll
        for (int j = 0; j < 8; j++)
            #pragma unroll
            for (int v = 0; v < 4; v++) acc[mi][j][v] = 0.f;

    const int lrow = tid >> 2, lo16 = (tid & 3) * 16, lk8 = (tid & 3) * 8;
    #define LOAD_CHUNK_ASYNC(kb, soff) do {                                     \
        uint32_t _sb = sbase + (soff);                                          \
        long long ga = (mbase + lrow) * (long long)K + (kb) + lk8;              \
        long long gb = (long long)(nbase + lrow) * K + (kb) + lk8;              \
        uint32_t so = lrow * (SROW * 2) + lo16;                                 \
        cp16(_sb + so,        A + ga);                                          \
        cp16(_sb + MATB + so, B + gb);                                          \
        long long ga2 = (mbase + 64 + lrow) * (long long)K + (kb) + lk8;        \
        long long gb2 = (long long)(nbase + 64 + lrow) * K + (kb) + lk8;        \
        uint32_t so2 = (64 + lrow) * (SROW * 2) + lo16;                         \
        cp16(_sb + so2,        A + ga2);                                        \
        cp16(_sb + MATB + so2, B + gb2);                                        \
    } while (0)

    LOAD_CHUNK_ASYNC(0, 0);
    cp_commit();
    cp_wait0();
    __syncthreads();

    const int arow = lane & 15;
    const int asel = (lane >> 4) << 3;
    const int br   = lane & 7;
    const int bsel = (lane >> 3) & 3;
    const int bno  = br + ((bsel >> 1) << 3);
    const int bko  = (bsel & 1) << 3;

    for (int c = 0; c < NC; c++) {
        if (c + 1 < NC) {
            LOAD_CHUNK_ASYNC((c + 1) * KC, ((c + 1) & 1) * GSTAGE);
            cp_commit();
        }

        const uint32_t sb = sbase + (c & 1) * GSTAGE;
        #pragma unroll
        for (int ks = 0; ks < 2; ks++) {
            uint32_t a[2][4];
            const int acol = ks * 16 + asel;
            #pragma unroll
            for (int mi = 0; mi < 2; mi++) {
                uint32_t aoff = ((wm * 32 + mi * 16 + arow) * SROW + acol) * 2;
                ldm_x4(a[mi], sb + aoff);
            }
            #pragma unroll
            for (int jj = 0; jj < 4; jj++) {
                uint32_t bb[4];
                uint32_t boff = ((wn * 64 + jj * 16 + bno) * SROW + ks * 16 + bko) * 2;
                ldm_x4(bb, sb + MATB + boff);
                #pragma unroll
                for (int mi = 0; mi < 2; mi++) {
                    mma16816(acc[mi][2 * jj],     a[mi], bb);
                    mma16816(acc[mi][2 * jj + 1], a[mi], bb + 2);
                }
            }
        }
        cp_wait0();
        __syncthreads();
    }

    // ---- epilogue ----
    const int r0 = wm * 32 + (lane >> 2);
    const int cn = wn * 64 + ((lane & 3) << 1);
    #pragma unroll
    for (int mi = 0; mi < 2; mi++) {
        #pragma unroll
        for (int j = 0; j < 8; j++) {
            int col = nbase + cn + j * 8;
            long long rg0 = mbase + r0 + mi * 16;
            long long rg1 = rg0 + 8;
            float* d = acc[mi][j];
            if (epi == 0) {
                float b0 = bias[col], b1 = bias[col + 1];
                float v00 = fmaxf(d[0] + b0, 0.f), v01 = fmaxf(d[1] + b1, 0.f);
                float v10 = fmaxf(d[2] + b0, 0.f), v11 = fmaxf(d[3] + b1, 0.f);
                *(__half2*)(g_a + rg0 * NTOT + col) = __floats2half2_rn(v00, v01);
                *(__half2*)(g_a + rg1 * NTOT + col) = __floats2half2_rn(v10, v11);
            } else if (epi == 1) {
                float b0 = bias[col], b1 = bias[col + 1];
                const float2 rv0 = *(const float2*)(resid + rg0 * NTOT + col);
                const float2 rv1 = *(const float2*)(resid + rg1 * NTOT + col);
                *(float2*)(Of + rg0 * NTOT + col) = make_float2(d[0] + b0 + rv0.x, d[1] + b1 + rv0.y);
                *(float2*)(Of + rg1 * NTOT + col) = make_float2(d[2] + b0 + rv1.x, d[3] + b1 + rv1.y);
            } else {
                float b0 = g_bqkv[col], b1 = g_bqkv[col + 1];
                *(__half2*)(g_pkv + rg0 * NTOT + col) = __floats2half2_rn(d[0] + b0, d[1] + b1);
                *(__half2*)(g_pkv + rg1 * NTOT + col) = __floats2half2_rn(d[2] + b0, d[3] + b1);
            }
        }
    }
}

// ============================================================================
// launch
// ============================================================================
extern "C" void kernel_launch(void* const* d_in, const int* in_sizes, int n_in,
                              void* d_out, int out_size)
{
    (void)in_sizes; (void)n_in; (void)out_size;
    const float* gidx = (const float*)d_in[0];
    const float* lg1  = (const float*)d_in[1];
    const float* lb1  = (const float*)d_in[2];
    const float* lg2  = (const float*)d_in[3];
    const float* lb2  = (const float*)d_in[4];
    const float* Wp   = (const float*)d_in[5];
    const float* bp   = (const float*)d_in[6];
    const float* Wk   = (const float*)d_in[7];
    const float* bk   = (const float*)d_in[8];
    const float* Wv   = (const float*)d_in[9];
    const float* bv   = (const float*)d_in[10];
    const float* W1   = (const float*)d_in[11];
    const float* b1f  = (const float*)d_in[12];
    const float* W2   = (const float*)d_in[13];
    const float* b2f  = (const float*)d_in[14];
    float* out = (float*)d_out;

    cudaFuncSetAttribute(gemm_kernel, cudaFuncAttributeMaxDynamicSharedMemorySize, G_SMEM);
    cudaFuncSetAttribute(attn_kernel, cudaFuncAttributeMaxDynamicSharedMemorySize, AT_SMEM);

    convert_weights<<<4096, 256>>>(W1, W2, Wp, Wk, Wv, bp, bk, bv);
    ln1_kernel<<<MTOT / 8, 256>>>(gidx, lg1, lb1);
    // QKV: [65536 x 512] @ Wqkvt[1536 x 512]^T + bqkv -> fp16 g_pkv
    gemm_kernel<<<dim3(MTOT / 128, NQKV / 128), 256, G_SMEM>>>(nullptr, nullptr, nullptr, Cd, NQKV, 2);
    attn_kernel<<<MTOT / 8, 256, AT_SMEM>>>(gidx, lg2, lb2);
    // FFN1: relu -> g_a (fp16)
    gemm_kernel<<<dim3(MTOT / 128, FFd / 128), 256, G_SMEM>>>(b1f, nullptr, nullptr, Cd, FFd, 0);
    // FFN2: + b2 + idx -> out
    gemm_kernel<<<dim3(MTOT / 128, Cd / 128), 256, G_SMEM>>>(b2f, gidx, out, FFd, Cd, 1);
}